// round 3
// baseline (speedup 1.0000x reference)
#include <cuda_runtime.h>
#include <cuda_bf16.h>
#include <math.h>

// Problem constants
#define L_DIM 1024
#define B_DIM 8
#define E_DIM 1024
#define H_DIM 16
#define HD    64
#define M_ROWS (L_DIM * B_DIM)      // 8192
#define QKV_N  (3 * E_DIM)          // 3072
#define ROW3E  (3 * E_DIM)

// Scratch (allocation-free rule: __device__ globals)
__device__ float g_qkv[(size_t)M_ROWS * QKV_N];   // ~100.7 MB
__device__ float g_attn[(size_t)M_ROWS * E_DIM];  // ~33.6 MB

__device__ __forceinline__ float to_tf32(float x) {
    float y;
    asm("cvt.rna.tf32.f32 %0, %1;" : "=f"(y) : "f"(x));
    return y;
}

__device__ __forceinline__ void mma_tf32(float* c, const float* a, const float* b) {
    asm volatile(
        "mma.sync.aligned.m16n8k8.row.col.f32.tf32.tf32.f32 "
        "{%0,%1,%2,%3}, {%4,%5,%6,%7}, {%8,%9}, {%0,%1,%2,%3};\n"
        : "+f"(c[0]), "+f"(c[1]), "+f"(c[2]), "+f"(c[3])
        : "r"(__float_as_uint(a[0])), "r"(__float_as_uint(a[1])),
          "r"(__float_as_uint(a[2])), "r"(__float_as_uint(a[3])),
          "r"(__float_as_uint(b[0])), "r"(__float_as_uint(b[1])));
}

// ---------------------------------------------------------------------------
// TF32 GEMM, double-buffered + register-prefetch pipeline.
// C[M,N] = A[M,K] @ W[N,K]^T + bias[N]
// Block tile 128x128, K-tile 32, 256 threads = 8 warps, warp tile 64x32.
// One __syncthreads per k-tile; LDG latency hidden behind 64 MMAs.
// ---------------------------------------------------------------------------
#define GS 36
__global__ void __launch_bounds__(256) gemm_tf32_kernel(
    const float* __restrict__ A, const float* __restrict__ W,
    const float* __restrict__ bias, float* __restrict__ C,
    int M, int N, int K)
{
    extern __shared__ float smg[];
    float* Abuf[2] = { smg,                smg + 2 * 128 * GS };
    float* Wbuf[2] = { smg + 128 * GS,     smg + 3 * 128 * GS };

    const int tid  = threadIdx.x;
    const int wid  = tid >> 5;
    const int lane = tid & 31;
    const int g    = lane >> 2;
    const int tg   = lane & 3;
    const int wm   = (wid >> 2) * 64;
    const int wn   = (wid & 3) * 32;
    const int rowBase = blockIdx.y * 128;
    const int colBase = blockIdx.x * 128;

    // loader mapping: thread covers rows r0+32p, cols c4..c4+3
    const int r0 = tid >> 3;
    const int c4 = (tid & 7) * 4;
    const float* Aptr = A + (size_t)(rowBase + r0) * K + c4;
    const float* Wptr = W + (size_t)(colBase + r0) * K + c4;

    float4 ra[4], rw[4];

#define GEMM_LD(k0)                                                        \
    _Pragma("unroll")                                                      \
    for (int p = 0; p < 4; p++) {                                          \
        ra[p] = *(const float4*)(Aptr + (size_t)(p * 32) * K + (k0));      \
        rw[p] = *(const float4*)(Wptr + (size_t)(p * 32) * K + (k0));      \
    }

#define GEMM_ST(buf)                                                       \
    _Pragma("unroll")                                                      \
    for (int p = 0; p < 4; p++) {                                          \
        float4 av = ra[p], wv = rw[p];                                     \
        av.x = to_tf32(av.x); av.y = to_tf32(av.y);                        \
        av.z = to_tf32(av.z); av.w = to_tf32(av.w);                        \
        wv.x = to_tf32(wv.x); wv.y = to_tf32(wv.y);                        \
        wv.z = to_tf32(wv.z); wv.w = to_tf32(wv.w);                        \
        *(float4*)&Abuf[buf][(r0 + p * 32) * GS + c4] = av;                \
        *(float4*)&Wbuf[buf][(r0 + p * 32) * GS + c4] = wv;                \
    }

    float c[4][4][4];
#pragma unroll
    for (int mi = 0; mi < 4; mi++)
#pragma unroll
        for (int nj = 0; nj < 4; nj++)
#pragma unroll
            for (int r = 0; r < 4; r++) c[mi][nj][r] = 0.f;

    const int T = K >> 5;
    GEMM_LD(0);
    GEMM_ST(0);
    __syncthreads();

    for (int t = 0; t < T; t++) {
        const int cur = t & 1;
        if (t + 1 < T) { GEMM_LD((t + 1) << 5); }

        const float* As = Abuf[cur];
        const float* Ws = Wbuf[cur];
#pragma unroll
        for (int ks = 0; ks < 4; ks++) {
            const int kk = ks * 8;
            float a[4][4], b[4][2];
#pragma unroll
            for (int mi = 0; mi < 4; mi++) {
                int rr = wm + mi * 16 + g;
                a[mi][0] = As[(rr    ) * GS + kk + tg];
                a[mi][1] = As[(rr + 8) * GS + kk + tg];
                a[mi][2] = As[(rr    ) * GS + kk + tg + 4];
                a[mi][3] = As[(rr + 8) * GS + kk + tg + 4];
            }
#pragma unroll
            for (int nj = 0; nj < 4; nj++) {
                int n0 = wn + nj * 8 + g;
                b[nj][0] = Ws[n0 * GS + kk + tg];
                b[nj][1] = Ws[n0 * GS + kk + tg + 4];
            }
#pragma unroll
            for (int mi = 0; mi < 4; mi++)
#pragma unroll
                for (int nj = 0; nj < 4; nj++)
                    mma_tf32(c[mi][nj], a[mi], b[nj]);
        }

        if (t + 1 < T) { GEMM_ST(1 - cur); }
        __syncthreads();
    }

    // epilogue: + bias
#pragma unroll
    for (int mi = 0; mi < 4; mi++) {
#pragma unroll
        for (int nj = 0; nj < 4; nj++) {
            int row0 = rowBase + wm + mi * 16 + g;
            int col  = colBase + wn + nj * 8 + tg * 2;
            float b0 = bias[col], b1 = bias[col + 1];
            float2 v0 = make_float2(c[mi][nj][0] + b0, c[mi][nj][1] + b1);
            float2 v1 = make_float2(c[mi][nj][2] + b0, c[mi][nj][3] + b1);
            *(float2*)(C + (size_t)row0 * N + col)       = v0;
            *(float2*)(C + (size_t)(row0 + 8) * N + col) = v1;
        }
    }
#undef GEMM_LD
#undef GEMM_ST
}

// ---------------------------------------------------------------------------
// TF32 flash attention, double-buffered K/V + register prefetch.
// One block = (b,h) x 128 query rows, 256 thr (8 warps), warp owns 16 S rows.
// One __syncthreads per kv-tile.
// ---------------------------------------------------------------------------
#define FS 68
__global__ void __launch_bounds__(256) flash_tf32_kernel(
    const float* __restrict__ qkv, float* __restrict__ outp)
{
    extern __shared__ float sm[];
    float* Kb[2] = { sm,               sm + 2 * 64 * FS };
    float* Vb[2] = { sm + 64 * FS,     sm + 3 * 64 * FS };
    float* Ps    = sm + 4 * 64 * FS;   // [128][FS], also Q staging

    const int tid  = threadIdx.x;
    const int wid  = tid >> 5;
    const int lane = tid & 31;
    const int g    = lane >> 2;
    const int tg   = lane & 3;
    const int wrow = wid * 16;

    const int bh = blockIdx.y;
    const int b  = bh >> 4;
    const int h  = bh & 15;
    const int q0 = blockIdx.x * 128;

    const size_t rstride = (size_t)B_DIM * ROW3E;  // 24576

    // loader mapping: rows r0+16p, cols c4..c4+3 of a 64x64 tile
    const int r0 = tid >> 4;
    const int c4 = (tid & 15) * 4;
    const float* kbase0 = qkv + (size_t)b * ROW3E + E_DIM + h * HD;
    float4 rk[4], rv[4];

#define KV_LD(kt)                                                            \
    _Pragma("unroll")                                                        \
    for (int p = 0; p < 4; p++) {                                            \
        const float* kb_ = kbase0 + (size_t)((kt) * 64 + r0 + p * 16) * rstride + c4; \
        rk[p] = *(const float4*)kb_;                                         \
        rv[p] = *(const float4*)(kb_ + E_DIM);                               \
    }

#define KV_ST(buf)                                                           \
    _Pragma("unroll")                                                        \
    for (int p = 0; p < 4; p++) {                                            \
        float4 kv = rk[p], vv = rv[p];                                       \
        kv.x = to_tf32(kv.x); kv.y = to_tf32(kv.y);                          \
        kv.z = to_tf32(kv.z); kv.w = to_tf32(kv.w);                          \
        vv.x = to_tf32(vv.x); vv.y = to_tf32(vv.y);                          \
        vv.z = to_tf32(vv.z); vv.w = to_tf32(vv.w);                          \
        *(float4*)&Kb[buf][(r0 + p * 16) * FS + c4] = kv;                    \
        *(float4*)&Vb[buf][(r0 + p * 16) * FS + c4] = vv;                    \
    }

    // ---- stage Q (scaled, tf32) into Ps, and KV tile 0 into buf0 ----
    {
        const float* qbase = qkv + (size_t)(q0 * B_DIM + b) * ROW3E + h * HD;
#pragma unroll
        for (int p = 0; p < 8; p++) {
            int f4 = tid + p * 256;
            int r  = f4 >> 4;
            int cc = (f4 & 15) * 4;
            float4 v = *(const float4*)(qbase + (size_t)r * rstride + cc);
            v.x = to_tf32(v.x * 0.125f); v.y = to_tf32(v.y * 0.125f);
            v.z = to_tf32(v.z * 0.125f); v.w = to_tf32(v.w * 0.125f);
            *(float4*)&Ps[r * FS + cc] = v;
        }
    }
    KV_LD(0);
    KV_ST(0);
    __syncthreads();

    // ---- Q fragments in registers for the whole kv loop ----
    float qa[8][4];
#pragma unroll
    for (int ks = 0; ks < 8; ks++) {
        int rr = wrow + g;
        int kk = ks * 8;
        qa[ks][0] = Ps[(rr    ) * FS + kk + tg];
        qa[ks][1] = Ps[(rr + 8) * FS + kk + tg];
        qa[ks][2] = Ps[(rr    ) * FS + kk + tg + 4];
        qa[ks][3] = Ps[(rr + 8) * FS + kk + tg + 4];
    }

    float o[8][4];
#pragma unroll
    for (int nj = 0; nj < 8; nj++)
#pragma unroll
        for (int r = 0; r < 4; r++) o[nj][r] = 0.f;
    float m0 = -1e30f, m1 = -1e30f, l0 = 0.f, l1 = 0.f;

    for (int kt = 0; kt < 16; kt++) {
        const int cur = kt & 1;
        if (kt + 1 < 16) { KV_LD(kt + 1); }

        const float* Ks = Kb[cur];
        const float* Vs = Vb[cur];

        // ---- S = Q K^T ----
        float s[8][4];
#pragma unroll
        for (int nj = 0; nj < 8; nj++)
#pragma unroll
            for (int r = 0; r < 4; r++) s[nj][r] = 0.f;

#pragma unroll
        for (int ks = 0; ks < 8; ks++) {
            const int kk = ks * 8;
            float kb[8][2];
#pragma unroll
            for (int nj = 0; nj < 8; nj++) {
                int tok = nj * 8 + g;
                kb[nj][0] = Ks[tok * FS + kk + tg];
                kb[nj][1] = Ks[tok * FS + kk + tg + 4];
            }
#pragma unroll
            for (int nj = 0; nj < 8; nj++)
                mma_tf32(s[nj], qa[ks], kb[nj]);
        }

        // ---- online softmax (rows g and g+8 of this warp) ----
        float rmax0 = -1e30f, rmax1 = -1e30f;
#pragma unroll
        for (int nj = 0; nj < 8; nj++) {
            rmax0 = fmaxf(rmax0, fmaxf(s[nj][0], s[nj][1]));
            rmax1 = fmaxf(rmax1, fmaxf(s[nj][2], s[nj][3]));
        }
        rmax0 = fmaxf(rmax0, __shfl_xor_sync(0xffffffffu, rmax0, 1));
        rmax0 = fmaxf(rmax0, __shfl_xor_sync(0xffffffffu, rmax0, 2));
        rmax1 = fmaxf(rmax1, __shfl_xor_sync(0xffffffffu, rmax1, 1));
        rmax1 = fmaxf(rmax1, __shfl_xor_sync(0xffffffffu, rmax1, 2));

        float nm0 = fmaxf(m0, rmax0), nm1 = fmaxf(m1, rmax1);
        float al0 = __expf(m0 - nm0), al1 = __expf(m1 - nm1);
        float rs0 = 0.f, rs1 = 0.f;
#pragma unroll
        for (int nj = 0; nj < 8; nj++) {
            s[nj][0] = __expf(s[nj][0] - nm0);
            s[nj][1] = __expf(s[nj][1] - nm0);
            s[nj][2] = __expf(s[nj][2] - nm1);
            s[nj][3] = __expf(s[nj][3] - nm1);
            rs0 += s[nj][0] + s[nj][1];
            rs1 += s[nj][2] + s[nj][3];
        }
        rs0 += __shfl_xor_sync(0xffffffffu, rs0, 1);
        rs0 += __shfl_xor_sync(0xffffffffu, rs0, 2);
        rs1 += __shfl_xor_sync(0xffffffffu, rs1, 1);
        rs1 += __shfl_xor_sync(0xffffffffu, rs1, 2);
        l0 = l0 * al0 + rs0;  m0 = nm0;
        l1 = l1 * al1 + rs1;  m1 = nm1;

#pragma unroll
        for (int nj = 0; nj < 8; nj++) {
            o[nj][0] *= al0; o[nj][1] *= al0;
            o[nj][2] *= al1; o[nj][3] *= al1;
        }

        // ---- write P (tf32) to warp-private smem slab ----
#pragma unroll
        for (int nj = 0; nj < 8; nj++) {
            int col = nj * 8 + tg * 2;
            float2 p0 = make_float2(to_tf32(s[nj][0]), to_tf32(s[nj][1]));
            float2 p1 = make_float2(to_tf32(s[nj][2]), to_tf32(s[nj][3]));
            *(float2*)&Ps[(wrow + g    ) * FS + col] = p0;
            *(float2*)&Ps[(wrow + g + 8) * FS + col] = p1;
        }
        __syncwarp();

        // ---- O += P @ V ----
#pragma unroll
        for (int ks = 0; ks < 8; ks++) {
            const int kk = ks * 8;
            float pa[4];
            int rr = wrow + g;
            pa[0] = Ps[(rr    ) * FS + kk + tg];
            pa[1] = Ps[(rr + 8) * FS + kk + tg];
            pa[2] = Ps[(rr    ) * FS + kk + tg + 4];
            pa[3] = Ps[(rr + 8) * FS + kk + tg + 4];
            float vb[8][2];
#pragma unroll
            for (int nj = 0; nj < 8; nj++) {
                int d = nj * 8 + g;
                vb[nj][0] = Vs[(kk + tg    ) * FS + d];
                vb[nj][1] = Vs[(kk + tg + 4) * FS + d];
            }
#pragma unroll
            for (int nj = 0; nj < 8; nj++)
                mma_tf32(o[nj], pa, vb[nj]);
        }

        if (kt + 1 < 16) { KV_ST(1 - cur); }
        __syncthreads();
    }

    // ---- epilogue: normalize, write to [L,B,E] at head offset ----
    float inv0 = 1.0f / l0, inv1 = 1.0f / l1;
#pragma unroll
    for (int nj = 0; nj < 8; nj++) {
        int col = h * HD + nj * 8 + tg * 2;
        int rr = q0 + wrow + g;
        float2 v0 = make_float2(o[nj][0] * inv0, o[nj][1] * inv0);
        float2 v1 = make_float2(o[nj][2] * inv1, o[nj][3] * inv1);
        *(float2*)(outp + (size_t)(rr * B_DIM + b) * E_DIM + col)       = v0;
        *(float2*)(outp + (size_t)((rr + 8) * B_DIM + b) * E_DIM + col) = v1;
    }
#undef KV_LD
#undef KV_ST
}

// ---------------------------------------------------------------------------
// Launch
// ---------------------------------------------------------------------------
extern "C" void kernel_launch(void* const* d_in, const int* in_sizes, int n_in,
                              void* d_out, int out_size)
{
    const float* x    = (const float*)d_in[0];
    const float* wqkv = (const float*)d_in[1];
    const float* bqkv = (const float*)d_in[2];
    const float* wout = (const float*)d_in[3];
    const float* bout = (const float*)d_in[4];
    float* out = (float*)d_out;

    float* qkv  = nullptr;
    float* attn = nullptr;
    cudaGetSymbolAddress((void**)&qkv,  g_qkv);
    cudaGetSymbolAddress((void**)&attn, g_attn);

    const size_t GEMM_SMEM  = (size_t)4 * 128 * GS * sizeof(float);              // 73728
    const size_t FLASH_SMEM = (size_t)(4 * 64 * FS + 128 * FS) * sizeof(float);  // 104448
    cudaFuncSetAttribute(gemm_tf32_kernel,
                         cudaFuncAttributeMaxDynamicSharedMemorySize, (int)GEMM_SMEM);
    cudaFuncSetAttribute(flash_tf32_kernel,
                         cudaFuncAttributeMaxDynamicSharedMemorySize, (int)FLASH_SMEM);

    // 1) QKV projection
    {
        dim3 grid(QKV_N / 128, M_ROWS / 128);
        gemm_tf32_kernel<<<grid, 256, GEMM_SMEM>>>(x, wqkv, bqkv, qkv, M_ROWS, QKV_N, E_DIM);
    }
    // 2) Attention
    {
        dim3 grid(L_DIM / 128, B_DIM * H_DIM);
        flash_tf32_kernel<<<grid, 256, FLASH_SMEM>>>(qkv, attn);
    }
    // 3) Output projection
    {
        dim3 grid(E_DIM / 128, M_ROWS / 128);
        gemm_tf32_kernel<<<grid, 256, GEMM_SMEM>>>(attn, wout, bout, out, M_ROWS, E_DIM, E_DIM);
    }
}

// round 4
// speedup vs baseline: 1.3590x; 1.3590x over previous
#include <cuda_runtime.h>
#include <cuda_bf16.h>
#include <math.h>
#include <stdint.h>

// Problem constants
#define L_DIM 1024
#define B_DIM 8
#define E_DIM 1024
#define H_DIM 16
#define HD    64
#define M_ROWS (L_DIM * B_DIM)      // 8192
#define QKV_N  (3 * E_DIM)          // 3072
#define ROW3E  (3 * E_DIM)

// Scratch (allocation-free rule: __device__ globals)
__device__ float g_qkv[(size_t)M_ROWS * QKV_N];   // rounded tf32, Q pre-scaled
__device__ float g_attn[(size_t)M_ROWS * E_DIM];  // rounded tf32
__device__ float g_xr[(size_t)M_ROWS * E_DIM];    // rounded x
__device__ float g_wqkvr[(size_t)QKV_N * E_DIM];  // rounded Wqkv
__device__ float g_woutr[(size_t)E_DIM * E_DIM];  // rounded Wout

__device__ __forceinline__ float to_tf32(float x) {
    float y;
    asm("cvt.rna.tf32.f32 %0, %1;" : "=f"(y) : "f"(x));
    return y;
}

__device__ __forceinline__ void mma_tf32(float* c, const uint32_t* a, const uint32_t* b) {
    asm volatile(
        "mma.sync.aligned.m16n8k8.row.col.f32.tf32.tf32.f32 "
        "{%0,%1,%2,%3}, {%4,%5,%6,%7}, {%8,%9}, {%0,%1,%2,%3};\n"
        : "+f"(c[0]), "+f"(c[1]), "+f"(c[2]), "+f"(c[3])
        : "r"(a[0]), "r"(a[1]), "r"(a[2]), "r"(a[3]),
          "r"(b[0]), "r"(b[1]));
}

__device__ __forceinline__ void cp16(uint32_t sdst, const void* gsrc) {
    asm volatile("cp.async.cg.shared.global [%0], [%1], 16;\n"
                 :: "r"(sdst), "l"(gsrc));
}
__device__ __forceinline__ void cp_commit() {
    asm volatile("cp.async.commit_group;\n" ::: "memory");
}
__device__ __forceinline__ void cp_wait0() {
    asm volatile("cp.async.wait_group 0;\n" ::: "memory");
}

__device__ __forceinline__ void ldm_x4(uint32_t* r, uint32_t addr) {
    asm volatile("ldmatrix.sync.aligned.m8n8.x4.shared.b16 {%0,%1,%2,%3}, [%4];"
        : "=r"(r[0]), "=r"(r[1]), "=r"(r[2]), "=r"(r[3]) : "r"(addr));
}
__device__ __forceinline__ void ldm_x2(uint32_t* r, uint32_t addr) {
    asm volatile("ldmatrix.sync.aligned.m8n8.x2.shared.b16 {%0,%1}, [%2];"
        : "=r"(r[0]), "=r"(r[1]) : "r"(addr));
}

// ---------------------------------------------------------------------------
// Prepass: round fp32 array to tf32 (float4 granularity)
// ---------------------------------------------------------------------------
__global__ void round_tf32_kernel(const float4* __restrict__ src,
                                  float4* __restrict__ dst, int n4)
{
    int i = blockIdx.x * blockDim.x + threadIdx.x;
    if (i < n4) {
        float4 v = src[i];
        v.x = to_tf32(v.x); v.y = to_tf32(v.y);
        v.z = to_tf32(v.z); v.w = to_tf32(v.w);
        dst[i] = v;
    }
}

// ---------------------------------------------------------------------------
// TF32 GEMM, cp.async double-buffer + ldmatrix.
// C[M,N] = A[M,K] @ W[N,K]^T + bias[N]
// Block tile 128x128, K-tile 32, 256 thr = 8 warps (64x32 each), 2 CTAs/SM.
// A,W must be pre-rounded to tf32 bits.
// MODE 0: plain fp32 out.  MODE 1: qkv out (round, scale Q section by 0.125).
// ---------------------------------------------------------------------------
#define GS 36
template<int MODE>
__global__ void __launch_bounds__(256, 2) gemm_tf32_kernel(
    const float* __restrict__ A, const float* __restrict__ W,
    const float* __restrict__ bias, float* __restrict__ C,
    int M, int N, int K)
{
    extern __shared__ float smg[];
    const int STAGEF = 2 * 128 * GS;   // floats per stage (A tile + W tile)
    const uint32_t sbase = (uint32_t)__cvta_generic_to_shared(smg);

    const int tid  = threadIdx.x;
    const int lane = tid & 31;
    const int wid  = tid >> 5;
    const int wm   = (wid >> 2) * 64;
    const int wn   = (wid & 3) * 32;
    const int rowBase = blockIdx.y * 128;
    const int colBase = blockIdx.x * 128;

    // cp.async loader mapping: rows r0+32p, 16B chunk c4
    const int r0 = tid >> 3;
    const int c4 = (tid & 7) * 4;
    const float* Aptr = A + (size_t)(rowBase + r0) * K + c4;
    const float* Wptr = W + (size_t)(colBase + r0) * K + c4;

    // ldmatrix per-lane address components
    const int arow = (lane & 15);          // + wm + mi*16
    const int acol = (lane & 16) >> 2;     // 0 or 4
    const int brow = (lane & 7);           // + wn + nj*8
    const int bcol = (lane & 8) >> 1;      // 0 or 4

    float c[4][4][4];
#pragma unroll
    for (int mi = 0; mi < 4; mi++)
#pragma unroll
        for (int nj = 0; nj < 4; nj++)
#pragma unroll
            for (int r = 0; r < 4; r++) c[mi][nj][r] = 0.f;

#define GEMM_STAGE(buf, k0)                                                    \
    {                                                                          \
        uint32_t sb_ = sbase + (uint32_t)((buf) * STAGEF) * 4u;                \
        _Pragma("unroll")                                                      \
        for (int p = 0; p < 4; p++) {                                          \
            cp16(sb_ + (uint32_t)(((r0 + p * 32) * GS + c4) * 4),              \
                 Aptr + (size_t)(p * 32) * K + (k0));                          \
            cp16(sb_ + (uint32_t)((128 * GS + (r0 + p * 32) * GS + c4) * 4),   \
                 Wptr + (size_t)(p * 32) * K + (k0));                          \
        }                                                                      \
        cp_commit();                                                           \
    }

    const int T = K >> 5;
    GEMM_STAGE(0, 0);
    cp_wait0();
    __syncthreads();

    for (int t = 0; t < T; t++) {
        const int cur = t & 1;
        if (t + 1 < T) GEMM_STAGE(1 - cur, (t + 1) << 5);

        const uint32_t Ab = sbase + (uint32_t)(cur * STAGEF) * 4u;
        const uint32_t Wb = Ab + (uint32_t)(128 * GS) * 4u;
#pragma unroll
        for (int ks = 0; ks < 4; ks++) {
            const int kk = ks * 8;
            uint32_t a[4][4], b[4][2];
#pragma unroll
            for (int mi = 0; mi < 4; mi++)
                ldm_x4(a[mi], Ab + (uint32_t)((((wm + mi * 16 + arow) * GS) + kk + acol) * 4));
#pragma unroll
            for (int nj = 0; nj < 4; nj++)
                ldm_x2(b[nj], Wb + (uint32_t)((((wn + nj * 8 + brow) * GS) + kk + bcol) * 4));
#pragma unroll
            for (int mi = 0; mi < 4; mi++)
#pragma unroll
                for (int nj = 0; nj < 4; nj++)
                    mma_tf32(c[mi][nj], a[mi], b[nj]);
        }
        if (t + 1 < T) cp_wait0();
        __syncthreads();
    }

    // epilogue
    const int g  = lane >> 2;
    const int tg = lane & 3;
    float scale = 1.f;
    if (MODE == 1) scale = (colBase < E_DIM) ? 0.125f : 1.f;
#pragma unroll
    for (int mi = 0; mi < 4; mi++) {
#pragma unroll
        for (int nj = 0; nj < 4; nj++) {
            int row0 = rowBase + wm + mi * 16 + g;
            int col  = colBase + wn + nj * 8 + tg * 2;
            float b0 = bias[col], b1 = bias[col + 1];
            float2 v0, v1;
            if (MODE == 1) {
                v0.x = to_tf32((c[mi][nj][0] + b0) * scale);
                v0.y = to_tf32((c[mi][nj][1] + b1) * scale);
                v1.x = to_tf32((c[mi][nj][2] + b0) * scale);
                v1.y = to_tf32((c[mi][nj][3] + b1) * scale);
            } else {
                v0.x = c[mi][nj][0] + b0; v0.y = c[mi][nj][1] + b1;
                v1.x = c[mi][nj][2] + b0; v1.y = c[mi][nj][3] + b1;
            }
            *(float2*)(C + (size_t)row0 * N + col)       = v0;
            *(float2*)(C + (size_t)(row0 + 8) * N + col) = v1;
        }
    }
#undef GEMM_STAGE
}

// ---------------------------------------------------------------------------
// TF32 flash attention. One block = (b,h) x 128 q-rows, 256 thr (8 warps),
// warp owns 16 S rows. qkv pre-rounded (Q pre-scaled). cp.async staging,
// ldmatrix for Q/K/P fragments; scalar LDS for V.
// smem: Qs[128][68], Ks[64][68], Vs[64][68], Ps[128][68] = 104448 B.
// ---------------------------------------------------------------------------
#define FS 68
__global__ void __launch_bounds__(256, 2) flash_tf32_kernel(
    const float* __restrict__ qkv, float* __restrict__ outp)
{
    extern __shared__ float sm[];
    float* Qs = sm;                      // 128*FS
    float* Ks = Qs + 128 * FS;           // 64*FS
    float* Vs = Ks + 64 * FS;            // 64*FS
    float* Ps = Vs + 64 * FS;            // 128*FS
    const uint32_t sQ = (uint32_t)__cvta_generic_to_shared(Qs);
    const uint32_t sK = (uint32_t)__cvta_generic_to_shared(Ks);
    const uint32_t sV = (uint32_t)__cvta_generic_to_shared(Vs);
    const uint32_t sP = (uint32_t)__cvta_generic_to_shared(Ps);

    const int tid  = threadIdx.x;
    const int wid  = tid >> 5;
    const int lane = tid & 31;
    const int g    = lane >> 2;
    const int tg   = lane & 3;
    const int wrow = wid * 16;

    const int bh = blockIdx.y;
    const int b  = bh >> 4;
    const int h  = bh & 15;
    const int q0 = blockIdx.x * 128;

    const size_t rstride = (size_t)B_DIM * ROW3E;  // 24576

    // ldmatrix lane address components
    const int arow = (lane & 15);
    const int acol = (lane & 16) >> 2;
    const int brow = (lane & 7);
    const int bcol = (lane & 8) >> 1;

    // loader mapping for 64x64 K/V tiles: rows r0+16p, chunk c4
    const int r0 = tid >> 4;
    const int c4 = (tid & 15) * 4;
    const float* kbase0 = qkv + (size_t)b * ROW3E + E_DIM + h * HD;

#define KV_STAGE(kt)                                                          \
    {                                                                         \
        _Pragma("unroll")                                                     \
        for (int p = 0; p < 4; p++) {                                         \
            int rr_ = r0 + p * 16;                                            \
            const float* kb_ = kbase0 + (size_t)((kt) * 64 + rr_) * rstride + c4; \
            cp16(sK + (uint32_t)((rr_ * FS + c4) * 4), kb_);                  \
            cp16(sV + (uint32_t)((rr_ * FS + c4) * 4), kb_ + E_DIM);          \
        }                                                                     \
        cp_commit();                                                          \
    }

    // ---- stage Q (already scaled+rounded) and KV tile 0 ----
    {
        const float* qbase = qkv + (size_t)(q0 * B_DIM + b) * ROW3E + h * HD;
#pragma unroll
        for (int p = 0; p < 8; p++) {
            int f4 = tid + p * 256;
            int r  = f4 >> 4;
            int cc = (f4 & 15) * 4;
            cp16(sQ + (uint32_t)((r * FS + cc) * 4),
                 qbase + (size_t)r * rstride + cc);
        }
    }
    KV_STAGE(0);
    cp_wait0();
    __syncthreads();

    float o[8][4];
#pragma unroll
    for (int nj = 0; nj < 8; nj++)
#pragma unroll
        for (int r = 0; r < 4; r++) o[nj][r] = 0.f;
    float m0 = -1e30f, m1 = -1e30f, l0 = 0.f, l1 = 0.f;

    for (int kt = 0; kt < 16; kt++) {
        // ---- S = Q K^T ----
        float s[8][4];
#pragma unroll
        for (int nj = 0; nj < 8; nj++)
#pragma unroll
            for (int r = 0; r < 4; r++) s[nj][r] = 0.f;

#pragma unroll
        for (int ks = 0; ks < 8; ks++) {
            const int kk = ks * 8;
            uint32_t qa[4];
            ldm_x4(qa, sQ + (uint32_t)((((wrow + arow) * FS) + kk + acol) * 4));
            uint32_t kb[8][2];
#pragma unroll
            for (int nj = 0; nj < 8; nj++)
                ldm_x2(kb[nj], sK + (uint32_t)((((nj * 8 + brow) * FS) + kk + bcol) * 4));
#pragma unroll
            for (int nj = 0; nj < 8; nj++)
                mma_tf32(s[nj], qa, kb[nj]);
        }

        // ---- online softmax (rows g and g+8 of this warp) ----
        float rmax0 = -1e30f, rmax1 = -1e30f;
#pragma unroll
        for (int nj = 0; nj < 8; nj++) {
            rmax0 = fmaxf(rmax0, fmaxf(s[nj][0], s[nj][1]));
            rmax1 = fmaxf(rmax1, fmaxf(s[nj][2], s[nj][3]));
        }
        rmax0 = fmaxf(rmax0, __shfl_xor_sync(0xffffffffu, rmax0, 1));
        rmax0 = fmaxf(rmax0, __shfl_xor_sync(0xffffffffu, rmax0, 2));
        rmax1 = fmaxf(rmax1, __shfl_xor_sync(0xffffffffu, rmax1, 1));
        rmax1 = fmaxf(rmax1, __shfl_xor_sync(0xffffffffu, rmax1, 2));

        float nm0 = fmaxf(m0, rmax0), nm1 = fmaxf(m1, rmax1);
        float al0 = __expf(m0 - nm0), al1 = __expf(m1 - nm1);
        float rs0 = 0.f, rs1 = 0.f;
#pragma unroll
        for (int nj = 0; nj < 8; nj++) {
            s[nj][0] = __expf(s[nj][0] - nm0);
            s[nj][1] = __expf(s[nj][1] - nm0);
            s[nj][2] = __expf(s[nj][2] - nm1);
            s[nj][3] = __expf(s[nj][3] - nm1);
            rs0 += s[nj][0] + s[nj][1];
            rs1 += s[nj][2] + s[nj][3];
        }
        rs0 += __shfl_xor_sync(0xffffffffu, rs0, 1);
        rs0 += __shfl_xor_sync(0xffffffffu, rs0, 2);
        rs1 += __shfl_xor_sync(0xffffffffu, rs1, 1);
        rs1 += __shfl_xor_sync(0xffffffffu, rs1, 2);
        l0 = l0 * al0 + rs0;  m0 = nm0;
        l1 = l1 * al1 + rs1;  m1 = nm1;

#pragma unroll
        for (int nj = 0; nj < 8; nj++) {
            o[nj][0] *= al0; o[nj][1] *= al0;
            o[nj][2] *= al1; o[nj][3] *= al1;
        }

        // ---- write P (tf32) to warp-private smem slab ----
#pragma unroll
        for (int nj = 0; nj < 8; nj++) {
            int col = nj * 8 + tg * 2;
            float2 p0 = make_float2(to_tf32(s[nj][0]), to_tf32(s[nj][1]));
            float2 p1 = make_float2(to_tf32(s[nj][2]), to_tf32(s[nj][3]));
            *(float2*)&Ps[(wrow + g    ) * FS + col] = p0;
            *(float2*)&Ps[(wrow + g + 8) * FS + col] = p1;
        }
        __syncwarp();

        // ---- O += P @ V ----
#pragma unroll
        for (int ks = 0; ks < 8; ks++) {
            const int kk = ks * 8;
            uint32_t pa[4];
            ldm_x4(pa, sP + (uint32_t)((((wrow + arow) * FS) + kk + acol) * 4));
            uint32_t vb[8][2];
#pragma unroll
            for (int nj = 0; nj < 8; nj++) {
                int d = nj * 8 + g;
                vb[nj][0] = __float_as_uint(Vs[(kk + tg    ) * FS + d]);
                vb[nj][1] = __float_as_uint(Vs[(kk + tg + 4) * FS + d]);
            }
#pragma unroll
            for (int nj = 0; nj < 8; nj++)
                mma_tf32(o[nj], pa, vb[nj]);
        }

        // ---- load next K/V tile ----
        __syncthreads();                 // everyone done with Ks/Vs
        if (kt + 1 < 16) {
            KV_STAGE(kt + 1);
            cp_wait0();
        }
        __syncthreads();
    }

    // ---- epilogue: normalize, round to tf32, write to [L,B,E] ----
    float inv0 = 1.0f / l0, inv1 = 1.0f / l1;
#pragma unroll
    for (int nj = 0; nj < 8; nj++) {
        int col = h * HD + nj * 8 + tg * 2;
        int rr = q0 + wrow + g;
        float2 v0 = make_float2(to_tf32(o[nj][0] * inv0), to_tf32(o[nj][1] * inv0));
        float2 v1 = make_float2(to_tf32(o[nj][2] * inv1), to_tf32(o[nj][3] * inv1));
        *(float2*)(outp + (size_t)(rr * B_DIM + b) * E_DIM + col)       = v0;
        *(float2*)(outp + (size_t)((rr + 8) * B_DIM + b) * E_DIM + col) = v1;
    }
#undef KV_STAGE
}

// ---------------------------------------------------------------------------
// Launch
// ---------------------------------------------------------------------------
extern "C" void kernel_launch(void* const* d_in, const int* in_sizes, int n_in,
                              void* d_out, int out_size)
{
    const float* x    = (const float*)d_in[0];
    const float* wqkv = (const float*)d_in[1];
    const float* bqkv = (const float*)d_in[2];
    const float* wout = (const float*)d_in[3];
    const float* bout = (const float*)d_in[4];
    float* out = (float*)d_out;

    float *qkv, *attn, *xr, *wqkvr, *woutr;
    cudaGetSymbolAddress((void**)&qkv,   g_qkv);
    cudaGetSymbolAddress((void**)&attn,  g_attn);
    cudaGetSymbolAddress((void**)&xr,    g_xr);
    cudaGetSymbolAddress((void**)&wqkvr, g_wqkvr);
    cudaGetSymbolAddress((void**)&woutr, g_woutr);

    const size_t GEMM_SMEM  = (size_t)4 * 128 * GS * sizeof(float);   // 73728
    const size_t FLASH_SMEM = (size_t)(384 * FS) * sizeof(float);     // 104448
    cudaFuncSetAttribute(gemm_tf32_kernel<1>,
                         cudaFuncAttributeMaxDynamicSharedMemorySize, (int)GEMM_SMEM);
    cudaFuncSetAttribute(gemm_tf32_kernel<0>,
                         cudaFuncAttributeMaxDynamicSharedMemorySize, (int)GEMM_SMEM);
    cudaFuncSetAttribute(flash_tf32_kernel,
                         cudaFuncAttributeMaxDynamicSharedMemorySize, (int)FLASH_SMEM);

    // 0) prepass: round inputs to tf32
    {
        int n4;
        n4 = M_ROWS * E_DIM / 4;
        round_tf32_kernel<<<(n4 + 255) / 256, 256>>>((const float4*)x, (float4*)xr, n4);
        n4 = QKV_N * E_DIM / 4;
        round_tf32_kernel<<<(n4 + 255) / 256, 256>>>((const float4*)wqkv, (float4*)wqkvr, n4);
        n4 = E_DIM * E_DIM / 4;
        round_tf32_kernel<<<(n4 + 255) / 256, 256>>>((const float4*)wout, (float4*)woutr, n4);
    }

    // 1) QKV projection (rounded output, Q pre-scaled)
    {
        dim3 grid(QKV_N / 128, M_ROWS / 128);
        gemm_tf32_kernel<1><<<grid, 256, GEMM_SMEM>>>(xr, wqkvr, bqkv, qkv,
                                                      M_ROWS, QKV_N, E_DIM);
    }
    // 2) Attention
    {
        dim3 grid(L_DIM / 128, B_DIM * H_DIM);
        flash_tf32_kernel<<<grid, 256, FLASH_SMEM>>>(qkv, attn);
    }
    // 3) Output projection (full fp32 output)
    {
        dim3 grid(E_DIM / 128, M_ROWS / 128);
        gemm_tf32_kernel<0><<<grid, 256, GEMM_SMEM>>>(attn, woutr, bout, out,
                                                      M_ROWS, E_DIM, E_DIM);
    }
}

// round 5
// speedup vs baseline: 1.4051x; 1.0339x over previous
#include <cuda_runtime.h>
#include <cuda_bf16.h>
#include <math.h>
#include <stdint.h>

// Problem constants
#define L_DIM 1024
#define B_DIM 8
#define E_DIM 1024
#define H_DIM 16
#define HD    64
#define M_ROWS (L_DIM * B_DIM)      // 8192
#define QKV_N  (3 * E_DIM)          // 3072
#define ROW3E  (3 * E_DIM)

// Scratch (allocation-free rule: __device__ globals)
__device__ float g_qkv[(size_t)M_ROWS * QKV_N];   // rounded tf32, Q pre-scaled
__device__ float g_attn[(size_t)M_ROWS * E_DIM];  // rounded tf32
__device__ float g_xr[(size_t)M_ROWS * E_DIM];    // rounded x
__device__ float g_wqkvr[(size_t)QKV_N * E_DIM];  // rounded Wqkv
__device__ float g_woutr[(size_t)E_DIM * E_DIM];  // rounded Wout

__device__ __forceinline__ float to_tf32(float x) {
    float y;
    asm("cvt.rna.tf32.f32 %0, %1;" : "=f"(y) : "f"(x));
    return y;
}

__device__ __forceinline__ void mma_tf32(float* c, const uint32_t* a, const uint32_t* b) {
    asm volatile(
        "mma.sync.aligned.m16n8k8.row.col.f32.tf32.tf32.f32 "
        "{%0,%1,%2,%3}, {%4,%5,%6,%7}, {%8,%9}, {%0,%1,%2,%3};\n"
        : "+f"(c[0]), "+f"(c[1]), "+f"(c[2]), "+f"(c[3])
        : "r"(a[0]), "r"(a[1]), "r"(a[2]), "r"(a[3]),
          "r"(b[0]), "r"(b[1]));
}

__device__ __forceinline__ void cp16(uint32_t sdst, const void* gsrc) {
    asm volatile("cp.async.cg.shared.global [%0], [%1], 16;\n"
                 :: "r"(sdst), "l"(gsrc));
}
__device__ __forceinline__ void cp_commit() {
    asm volatile("cp.async.commit_group;\n" ::: "memory");
}
__device__ __forceinline__ void cp_wait0() {
    asm volatile("cp.async.wait_group 0;\n" ::: "memory");
}

__device__ __forceinline__ void ldm_x4(uint32_t* r, uint32_t addr) {
    asm volatile("ldmatrix.sync.aligned.m8n8.x4.shared.b16 {%0,%1,%2,%3}, [%4];"
        : "=r"(r[0]), "=r"(r[1]), "=r"(r[2]), "=r"(r[3]) : "r"(addr));
}

// ---------------------------------------------------------------------------
// Prepass: round fp32 array to tf32
// ---------------------------------------------------------------------------
__global__ void round_tf32_kernel(const float4* __restrict__ src,
                                  float4* __restrict__ dst, int n4)
{
    int i = blockIdx.x * blockDim.x + threadIdx.x;
    if (i < n4) {
        float4 v = src[i];
        v.x = to_tf32(v.x); v.y = to_tf32(v.y);
        v.z = to_tf32(v.z); v.w = to_tf32(v.w);
        dst[i] = v;
    }
}

// ---------------------------------------------------------------------------
// TF32 GEMM: C[M,N] = A[M,K] @ W[N,K]^T + bias[N]
// 128 threads = 4 warps, block tile 128x128, warp tile 64x64 (2x2 warp grid),
// K-tile 32, cp.async double buffer, ldmatrix fragments, 2 CTAs/SM.
// Fragment smem traffic: A x2 + W x2 (vs x4+x2 with 8 warps) -> below crossbar cap.
// MODE 0: plain fp32 out.  MODE 1: qkv out (round, scale Q columns by 0.125).
// ---------------------------------------------------------------------------
#define GS 36
template<int MODE>
__global__ void __launch_bounds__(128, 2) gemm_tf32_kernel(
    const float* __restrict__ A, const float* __restrict__ W,
    const float* __restrict__ bias, float* __restrict__ C,
    int M, int N, int K)
{
    extern __shared__ float smg[];
    const int STAGEF = 2 * 128 * GS;
    const uint32_t sbase = (uint32_t)__cvta_generic_to_shared(smg);

    const int tid  = threadIdx.x;
    const int lane = tid & 31;
    const int wid  = tid >> 5;
    const int wm   = (wid >> 1) * 64;
    const int wn   = (wid & 1) * 64;
    const int rowBase = blockIdx.y * 128;
    const int colBase = blockIdx.x * 128;

    // cp.async loader: chunk = tid + p*128 -> row = (tid>>3)+p*16, col = (tid&7)*4
    const int r0 = tid >> 3;
    const int c4 = (tid & 7) * 4;
    const float* Aptr = A + (size_t)(rowBase + r0) * K + c4;
    const float* Wptr = W + (size_t)(colBase + r0) * K + c4;

    // ldmatrix lane address components
    const int arow = (lane & 15);          // A: rows, lanes 0-15 col kk, 16-31 col kk+4
    const int acol = (lane & 16) >> 2;
    const int bm   = lane >> 3;            // B: 4 matrices over 16 rows x 8 k
    const int brow = ((bm >> 1) << 3) + (lane & 7);
    const int bcol = (bm & 1) << 2;

    float c[4][8][4];
#pragma unroll
    for (int mi = 0; mi < 4; mi++)
#pragma unroll
        for (int nj = 0; nj < 8; nj++)
#pragma unroll
            for (int r = 0; r < 4; r++) c[mi][nj][r] = 0.f;

#define GEMM_STAGE(buf, k0)                                                    \
    {                                                                          \
        uint32_t sb_ = sbase + (uint32_t)((buf) * STAGEF) * 4u;                \
        _Pragma("unroll")                                                      \
        for (int p = 0; p < 8; p++) {                                          \
            cp16(sb_ + (uint32_t)(((r0 + p * 16) * GS + c4) * 4),              \
                 Aptr + (size_t)(p * 16) * K + (k0));                          \
            cp16(sb_ + (uint32_t)((128 * GS + (r0 + p * 16) * GS + c4) * 4),   \
                 Wptr + (size_t)(p * 16) * K + (k0));                          \
        }                                                                      \
        cp_commit();                                                           \
    }

    const int T = K >> 5;
    GEMM_STAGE(0, 0);
    cp_wait0();
    __syncthreads();

    for (int t = 0; t < T; t++) {
        const int cur = t & 1;
        if (t + 1 < T) GEMM_STAGE(1 - cur, (t + 1) << 5);

        const uint32_t Ab = sbase + (uint32_t)(cur * STAGEF) * 4u;
        const uint32_t Wb = Ab + (uint32_t)(128 * GS) * 4u;
#pragma unroll
        for (int ks = 0; ks < 4; ks++) {
            const int kk = ks * 8;
            uint32_t a[4][4], b[8][2];
#pragma unroll
            for (int mi = 0; mi < 4; mi++)
                ldm_x4(a[mi], Ab + (uint32_t)((((wm + mi * 16 + arow) * GS) + kk + acol) * 4));
#pragma unroll
            for (int njp = 0; njp < 4; njp++)
                ldm_x4(&b[njp * 2][0],
                       Wb + (uint32_t)((((wn + njp * 16 + brow) * GS) + kk + bcol) * 4));
#pragma unroll
            for (int mi = 0; mi < 4; mi++)
#pragma unroll
                for (int nj = 0; nj < 8; nj++)
                    mma_tf32(c[mi][nj], a[mi], b[nj]);
        }
        if (t + 1 < T) cp_wait0();
        __syncthreads();
    }

    // epilogue
    const int g  = lane >> 2;
    const int tg = lane & 3;
    float scale = 1.f;
    if (MODE == 1) scale = (colBase < E_DIM) ? 0.125f : 1.f;
#pragma unroll
    for (int mi = 0; mi < 4; mi++) {
#pragma unroll
        for (int nj = 0; nj < 8; nj++) {
            int row0 = rowBase + wm + mi * 16 + g;
            int col  = colBase + wn + nj * 8 + tg * 2;
            float b0 = bias[col], b1 = bias[col + 1];
            float2 v0, v1;
            if (MODE == 1) {
                v0.x = to_tf32((c[mi][nj][0] + b0) * scale);
                v0.y = to_tf32((c[mi][nj][1] + b1) * scale);
                v1.x = to_tf32((c[mi][nj][2] + b0) * scale);
                v1.y = to_tf32((c[mi][nj][3] + b1) * scale);
            } else {
                v0.x = c[mi][nj][0] + b0; v0.y = c[mi][nj][1] + b1;
                v1.x = c[mi][nj][2] + b0; v1.y = c[mi][nj][3] + b1;
            }
            *(float2*)(C + (size_t)row0 * N + col)       = v0;
            *(float2*)(C + (size_t)(row0 + 8) * N + col) = v1;
        }
    }
#undef GEMM_STAGE
}

// ---------------------------------------------------------------------------
// TF32 flash attention, double-buffered K/V with prefetch-at-top.
// One block = (b,h) x 128 q-rows, 256 thr (8 warps), warp owns 16 S rows.
// Q fragments live in registers (loaded once). Ps slab: Q staging, then P.
// smem: 2xK(64x68) + 2xV(64x68) + Ps(128x68) = 104448 B -> 2 CTAs/SM.
// ---------------------------------------------------------------------------
#define FS 68
__global__ void __launch_bounds__(256, 2) flash_tf32_kernel(
    const float* __restrict__ qkv, float* __restrict__ outp)
{
    extern __shared__ float sm[];
    float* Kb0 = sm;                     // 64*FS
    float* Vb0 = Kb0 + 64 * FS;
    float* Kb1 = Vb0 + 64 * FS;
    float* Vb1 = Kb1 + 64 * FS;
    float* Ps  = Vb1 + 64 * FS;          // 128*FS
    const uint32_t sK0 = (uint32_t)__cvta_generic_to_shared(Kb0);
    const uint32_t sP  = (uint32_t)__cvta_generic_to_shared(Ps);
    const uint32_t KVSTRIDE = (uint32_t)(2 * 64 * FS) * 4u;  // K0->K1 byte offset

    const int tid  = threadIdx.x;
    const int wid  = tid >> 5;
    const int lane = tid & 31;
    const int g    = lane >> 2;
    const int tg   = lane & 3;
    const int wrow = wid * 16;

    const int bh = blockIdx.y;
    const int b  = bh >> 4;
    const int h  = bh & 15;
    const int q0 = blockIdx.x * 128;

    const size_t rstride = (size_t)B_DIM * ROW3E;  // 24576

    // ldmatrix lane address components
    const int arow = (lane & 15);
    const int acol = (lane & 16) >> 2;
    const int bm   = lane >> 3;
    const int brow = ((bm >> 1) << 3) + (lane & 7);
    const int bcol = (bm & 1) << 2;

    // K/V tile loader: rows r0+p*16, chunk c4
    const int r0 = tid >> 4;
    const int c4 = (tid & 15) * 4;
    const float* kbase0 = qkv + (size_t)b * ROW3E + E_DIM + h * HD;

#define KV_STAGE(kt, buf)                                                     \
    {                                                                         \
        uint32_t sKb_ = sK0 + (buf) * KVSTRIDE;                               \
        uint32_t sVb_ = sKb_ + (uint32_t)(64 * FS) * 4u;                      \
        _Pragma("unroll")                                                     \
        for (int p = 0; p < 4; p++) {                                         \
            int rr_ = r0 + p * 16;                                            \
            const float* kb_ = kbase0 + (size_t)((kt) * 64 + rr_) * rstride + c4; \
            cp16(sKb_ + (uint32_t)((rr_ * FS + c4) * 4), kb_);                \
            cp16(sVb_ + (uint32_t)((rr_ * FS + c4) * 4), kb_ + E_DIM);        \
        }                                                                     \
        cp_commit();                                                          \
    }

    // ---- stage Q (pre-scaled tf32) into Ps, and KV tile 0 ----
    {
        const float* qbase = qkv + (size_t)(q0 * B_DIM + b) * ROW3E + h * HD;
#pragma unroll
        for (int p = 0; p < 8; p++) {
            int f4 = tid + p * 256;
            int r  = f4 >> 4;
            int cc = (f4 & 15) * 4;
            cp16(sP + (uint32_t)((r * FS + cc) * 4),
                 qbase + (size_t)r * rstride + cc);
        }
    }
    KV_STAGE(0, 0);
    cp_wait0();
    __syncthreads();

    // ---- Q fragments into registers (warp reads only its own 16 rows) ----
    uint32_t qa[8][4];
#pragma unroll
    for (int ks = 0; ks < 8; ks++)
        ldm_x4(qa[ks], sP + (uint32_t)((((wrow + arow) * FS) + ks * 8 + acol) * 4));
    __syncwarp();

    float o[8][4];
#pragma unroll
    for (int nj = 0; nj < 8; nj++)
#pragma unroll
        for (int r = 0; r < 4; r++) o[nj][r] = 0.f;
    float m0 = -1e30f, m1 = -1e30f, l0 = 0.f, l1 = 0.f;

    for (int kt = 0; kt < 16; kt++) {
        const int cur = kt & 1;
        if (kt + 1 < 16) KV_STAGE(kt + 1, 1 - cur);

        const uint32_t sKc = sK0 + cur * KVSTRIDE;
        const float* Vs = (cur ? Vb1 : Vb0);

        // ---- S = Q K^T ----
        float s[8][4];
#pragma unroll
        for (int nj = 0; nj < 8; nj++)
#pragma unroll
            for (int r = 0; r < 4; r++) s[nj][r] = 0.f;

#pragma unroll
        for (int ks = 0; ks < 8; ks++) {
            const int kk = ks * 8;
            uint32_t kb[8][2];
#pragma unroll
            for (int njp = 0; njp < 4; njp++)
                ldm_x4(&kb[njp * 2][0],
                       sKc + (uint32_t)((((njp * 16 + brow) * FS) + kk + bcol) * 4));
#pragma unroll
            for (int nj = 0; nj < 8; nj++)
                mma_tf32(s[nj], qa[ks], kb[nj]);
        }

        // ---- online softmax (rows g and g+8 of this warp) ----
        float rmax0 = -1e30f, rmax1 = -1e30f;
#pragma unroll
        for (int nj = 0; nj < 8; nj++) {
            rmax0 = fmaxf(rmax0, fmaxf(s[nj][0], s[nj][1]));
            rmax1 = fmaxf(rmax1, fmaxf(s[nj][2], s[nj][3]));
        }
        rmax0 = fmaxf(rmax0, __shfl_xor_sync(0xffffffffu, rmax0, 1));
        rmax0 = fmaxf(rmax0, __shfl_xor_sync(0xffffffffu, rmax0, 2));
        rmax1 = fmaxf(rmax1, __shfl_xor_sync(0xffffffffu, rmax1, 1));
        rmax1 = fmaxf(rmax1, __shfl_xor_sync(0xffffffffu, rmax1, 2));

        float nm0 = fmaxf(m0, rmax0), nm1 = fmaxf(m1, rmax1);
        float al0 = __expf(m0 - nm0), al1 = __expf(m1 - nm1);
        float rs0 = 0.f, rs1 = 0.f;
#pragma unroll
        for (int nj = 0; nj < 8; nj++) {
            s[nj][0] = __expf(s[nj][0] - nm0);
            s[nj][1] = __expf(s[nj][1] - nm0);
            s[nj][2] = __expf(s[nj][2] - nm1);
            s[nj][3] = __expf(s[nj][3] - nm1);
            rs0 += s[nj][0] + s[nj][1];
            rs1 += s[nj][2] + s[nj][3];
        }
        rs0 += __shfl_xor_sync(0xffffffffu, rs0, 1);
        rs0 += __shfl_xor_sync(0xffffffffu, rs0, 2);
        rs1 += __shfl_xor_sync(0xffffffffu, rs1, 1);
        rs1 += __shfl_xor_sync(0xffffffffu, rs1, 2);
        l0 = l0 * al0 + rs0;  m0 = nm0;
        l1 = l1 * al1 + rs1;  m1 = nm1;

#pragma unroll
        for (int nj = 0; nj < 8; nj++) {
            o[nj][0] *= al0; o[nj][1] *= al0;
            o[nj][2] *= al1; o[nj][3] *= al1;
        }

        // ---- write P (tf32) to warp-private smem rows ----
#pragma unroll
        for (int nj = 0; nj < 8; nj++) {
            int col = nj * 8 + tg * 2;
            float2 p0 = make_float2(to_tf32(s[nj][0]), to_tf32(s[nj][1]));
            float2 p1 = make_float2(to_tf32(s[nj][2]), to_tf32(s[nj][3]));
            *(float2*)&Ps[(wrow + g    ) * FS + col] = p0;
            *(float2*)&Ps[(wrow + g + 8) * FS + col] = p1;
        }
        __syncwarp();

        // ---- O += P @ V ----
#pragma unroll
        for (int ks = 0; ks < 8; ks++) {
            const int kk = ks * 8;
            uint32_t pa[4];
            ldm_x4(pa, sP + (uint32_t)((((wrow + arow) * FS) + kk + acol) * 4));
            uint32_t vb[8][2];
#pragma unroll
            for (int nj = 0; nj < 8; nj++) {
                int d = nj * 8 + g;
                vb[nj][0] = __float_as_uint(Vs[(kk + tg    ) * FS + d]);
                vb[nj][1] = __float_as_uint(Vs[(kk + tg + 4) * FS + d]);
            }
#pragma unroll
            for (int nj = 0; nj < 8; nj++)
                mma_tf32(o[nj], pa, vb[nj]);
        }

        cp_wait0();       // next tile's K/V resident
        __syncthreads();  // all warps done with cur buffers
    }

    // ---- epilogue: normalize, round to tf32, write to [L,B,E] ----
    float inv0 = 1.0f / l0, inv1 = 1.0f / l1;
#pragma unroll
    for (int nj = 0; nj < 8; nj++) {
        int col = h * HD + nj * 8 + tg * 2;
        int rr = q0 + wrow + g;
        float2 v0 = make_float2(to_tf32(o[nj][0] * inv0), to_tf32(o[nj][1] * inv0));
        float2 v1 = make_float2(to_tf32(o[nj][2] * inv1), to_tf32(o[nj][3] * inv1));
        *(float2*)(outp + (size_t)(rr * B_DIM + b) * E_DIM + col)       = v0;
        *(float2*)(outp + (size_t)((rr + 8) * B_DIM + b) * E_DIM + col) = v1;
    }
#undef KV_STAGE
}

// ---------------------------------------------------------------------------
// Launch
// ---------------------------------------------------------------------------
extern "C" void kernel_launch(void* const* d_in, const int* in_sizes, int n_in,
                              void* d_out, int out_size)
{
    const float* x    = (const float*)d_in[0];
    const float* wqkv = (const float*)d_in[1];
    const float* bqkv = (const float*)d_in[2];
    const float* wout = (const float*)d_in[3];
    const float* bout = (const float*)d_in[4];
    float* out = (float*)d_out;

    float *qkv, *attn, *xr, *wqkvr, *woutr;
    cudaGetSymbolAddress((void**)&qkv,   g_qkv);
    cudaGetSymbolAddress((void**)&attn,  g_attn);
    cudaGetSymbolAddress((void**)&xr,    g_xr);
    cudaGetSymbolAddress((void**)&wqkvr, g_wqkvr);
    cudaGetSymbolAddress((void**)&woutr, g_woutr);

    const size_t GEMM_SMEM  = (size_t)4 * 128 * GS * sizeof(float);   // 73728
    const size_t FLASH_SMEM = (size_t)(384 * FS) * sizeof(float);     // 104448
    cudaFuncSetAttribute(gemm_tf32_kernel<1>,
                         cudaFuncAttributeMaxDynamicSharedMemorySize, (int)GEMM_SMEM);
    cudaFuncSetAttribute(gemm_tf32_kernel<0>,
                         cudaFuncAttributeMaxDynamicSharedMemorySize, (int)GEMM_SMEM);
    cudaFuncSetAttribute(flash_tf32_kernel,
                         cudaFuncAttributeMaxDynamicSharedMemorySize, (int)FLASH_SMEM);

    // 0) prepass: round inputs to tf32
    {
        int n4;
        n4 = M_ROWS * E_DIM / 4;
        round_tf32_kernel<<<(n4 + 255) / 256, 256>>>((const float4*)x, (float4*)xr, n4);
        n4 = QKV_N * E_DIM / 4;
        round_tf32_kernel<<<(n4 + 255) / 256, 256>>>((const float4*)wqkv, (float4*)wqkvr, n4);
        n4 = E_DIM * E_DIM / 4;
        round_tf32_kernel<<<(n4 + 255) / 256, 256>>>((const float4*)wout, (float4*)woutr, n4);
    }

    // 1) QKV projection (rounded output, Q pre-scaled)
    {
        dim3 grid(QKV_N / 128, M_ROWS / 128);
        gemm_tf32_kernel<1><<<grid, 128, GEMM_SMEM>>>(xr, wqkvr, bqkv, qkv,
                                                      M_ROWS, QKV_N, E_DIM);
    }
    // 2) Attention
    {
        dim3 grid(L_DIM / 128, B_DIM * H_DIM);
        flash_tf32_kernel<<<grid, 256, FLASH_SMEM>>>(qkv, attn);
    }
    // 3) Output projection (full fp32 output)
    {
        dim3 grid(E_DIM / 128, M_ROWS / 128);
        gemm_tf32_kernel<0><<<grid, 128, GEMM_SMEM>>>(attn, woutr, bout, out,
                                                      M_ROWS, E_DIM, E_DIM);
    }
}

// round 6
// speedup vs baseline: 1.4742x; 1.0492x over previous
#include <cuda_runtime.h>
#include <cuda_bf16.h>
#include <math.h>
#include <stdint.h>

// Problem constants
#define L_DIM 1024
#define B_DIM 8
#define E_DIM 1024
#define H_DIM 16
#define HD    64
#define M_ROWS (L_DIM * B_DIM)      // 8192
#define QKV_N  (3 * E_DIM)          // 3072
#define ROW3E  (3 * E_DIM)

// Scratch (allocation-free rule: __device__ globals)
__device__ float g_qkv[(size_t)M_ROWS * QKV_N];   // rounded tf32, Q pre-scaled
__device__ float g_attn[(size_t)M_ROWS * E_DIM];  // rounded tf32
__device__ float g_xr[(size_t)M_ROWS * E_DIM];    // rounded x
__device__ float g_wqkvr[(size_t)QKV_N * E_DIM];  // rounded Wqkv
__device__ float g_woutr[(size_t)E_DIM * E_DIM];  // rounded Wout

__device__ __forceinline__ float to_tf32(float x) {
    float y;
    asm("cvt.rna.tf32.f32 %0, %1;" : "=f"(y) : "f"(x));
    return y;
}

__device__ __forceinline__ void mma_tf32(float* c, const uint32_t* a, const uint32_t* b) {
    asm volatile(
        "mma.sync.aligned.m16n8k8.row.col.f32.tf32.tf32.f32 "
        "{%0,%1,%2,%3}, {%4,%5,%6,%7}, {%8,%9}, {%0,%1,%2,%3};\n"
        : "+f"(c[0]), "+f"(c[1]), "+f"(c[2]), "+f"(c[3])
        : "r"(a[0]), "r"(a[1]), "r"(a[2]), "r"(a[3]),
          "r"(b[0]), "r"(b[1]));
}

__device__ __forceinline__ void cp16(uint32_t sdst, const void* gsrc) {
    asm volatile("cp.async.cg.shared.global [%0], [%1], 16;\n"
                 :: "r"(sdst), "l"(gsrc));
}
__device__ __forceinline__ void cp_commit() {
    asm volatile("cp.async.commit_group;\n" ::: "memory");
}
__device__ __forceinline__ void cp_wait0() {
    asm volatile("cp.async.wait_group 0;\n" ::: "memory");
}
__device__ __forceinline__ void cp_wait1() {
    asm volatile("cp.async.wait_group 1;\n" ::: "memory");
}

__device__ __forceinline__ void ldm_x4(uint32_t* r, uint32_t addr) {
    asm volatile("ldmatrix.sync.aligned.m8n8.x4.shared.b16 {%0,%1,%2,%3}, [%4];"
        : "=r"(r[0]), "=r"(r[1]), "=r"(r[2]), "=r"(r[3]) : "r"(addr));
}

// ---------------------------------------------------------------------------
// Prepass: round fp32 array to tf32
// ---------------------------------------------------------------------------
__global__ void round_tf32_kernel(const float4* __restrict__ src,
                                  float4* __restrict__ dst, int n4)
{
    int i = blockIdx.x * blockDim.x + threadIdx.x;
    if (i < n4) {
        float4 v = src[i];
        v.x = to_tf32(v.x); v.y = to_tf32(v.y);
        v.z = to_tf32(v.z); v.w = to_tf32(v.w);
        dst[i] = v;
    }
}

// ---------------------------------------------------------------------------
// TF32 GEMM: C[M,N] = A[M,K] @ W[N,K]^T + bias[N]
// 256 threads = 8 warps (2x4 grid of 64x32 warp tiles), block tile 128x128,
// K-tile 32, 3-stage cp.async pipeline (loads get ~2 k-tiles to land),
// ldmatrix fragments, 2 CTAs/SM.
// MODE 0: plain fp32 out.  MODE 1: qkv out (round, scale Q columns by 0.125).
// ---------------------------------------------------------------------------
#define GS 36
template<int MODE>
__global__ void __launch_bounds__(256, 2) gemm_tf32_kernel(
    const float* __restrict__ A, const float* __restrict__ W,
    const float* __restrict__ bias, float* __restrict__ C,
    int M, int N, int K)
{
    extern __shared__ float smg[];
    const int STAGEF = 2 * 128 * GS;   // floats per stage (A tile + W tile)
    const uint32_t sbase = (uint32_t)__cvta_generic_to_shared(smg);

    const int tid  = threadIdx.x;
    const int lane = tid & 31;
    const int wid  = tid >> 5;
    const int wm   = (wid >> 2) * 64;
    const int wn   = (wid & 3) * 32;
    const int rowBase = blockIdx.y * 128;
    const int colBase = blockIdx.x * 128;

    // cp.async loader mapping: rows r0+32p, 16B chunk c4
    const int r0 = tid >> 3;
    const int c4 = (tid & 7) * 4;
    const float* Aptr = A + (size_t)(rowBase + r0) * K + c4;
    const float* Wptr = W + (size_t)(colBase + r0) * K + c4;

    // ldmatrix per-lane address components
    const int arow = (lane & 15);
    const int acol = (lane & 16) >> 2;
    const int bm   = lane >> 3;           // B: x4 over 16 rows x 8 k
    const int brow = ((bm >> 1) << 3) + (lane & 7);
    const int bcol = (bm & 1) << 2;

    float c[4][4][4];
#pragma unroll
    for (int mi = 0; mi < 4; mi++)
#pragma unroll
        for (int nj = 0; nj < 4; nj++)
#pragma unroll
            for (int r = 0; r < 4; r++) c[mi][nj][r] = 0.f;

#define GEMM_STAGE(buf, k0)                                                    \
    {                                                                          \
        uint32_t sb_ = sbase + (uint32_t)((buf) * STAGEF) * 4u;                \
        _Pragma("unroll")                                                      \
        for (int p = 0; p < 4; p++) {                                          \
            cp16(sb_ + (uint32_t)(((r0 + p * 32) * GS + c4) * 4),              \
                 Aptr + (size_t)(p * 32) * K + (k0));                          \
            cp16(sb_ + (uint32_t)((128 * GS + (r0 + p * 32) * GS + c4) * 4),   \
                 Wptr + (size_t)(p * 32) * K + (k0));                          \
        }                                                                      \
        cp_commit();                                                           \
    }

    const int T = K >> 5;        // >= 2 always here (K=1024)
    GEMM_STAGE(0, 0);
    GEMM_STAGE(1, 32);

    int cbuf = 0;
    for (int t = 0; t < T; t++) {
        // stage t resident (leave stage t+1 in flight, except last iter)
        if (t == T - 1) cp_wait0(); else cp_wait1();
        __syncthreads();

        if (t + 2 < T) {
            int nb = cbuf + 2; if (nb >= 3) nb -= 3;
            GEMM_STAGE(nb, (t + 2) << 5);
        }

        const uint32_t Ab = sbase + (uint32_t)(cbuf * STAGEF) * 4u;
        const uint32_t Wb = Ab + (uint32_t)(128 * GS) * 4u;
#pragma unroll
        for (int ks = 0; ks < 4; ks++) {
            const int kk = ks * 8;
            uint32_t a[4][4], b[4][2];
#pragma unroll
            for (int mi = 0; mi < 4; mi++)
                ldm_x4(a[mi], Ab + (uint32_t)((((wm + mi * 16 + arow) * GS) + kk + acol) * 4));
#pragma unroll
            for (int njp = 0; njp < 2; njp++)
                ldm_x4(&b[njp * 2][0],
                       Wb + (uint32_t)((((wn + njp * 16 + brow) * GS) + kk + bcol) * 4));
#pragma unroll
            for (int mi = 0; mi < 4; mi++)
#pragma unroll
                for (int nj = 0; nj < 4; nj++)
                    mma_tf32(c[mi][nj], a[mi], b[nj]);
        }
        cbuf++; if (cbuf == 3) cbuf = 0;
    }

    // epilogue
    const int g  = lane >> 2;
    const int tg = lane & 3;
    float scale = 1.f;
    if (MODE == 1) scale = (colBase < E_DIM) ? 0.125f : 1.f;
#pragma unroll
    for (int mi = 0; mi < 4; mi++) {
#pragma unroll
        for (int nj = 0; nj < 4; nj++) {
            int row0 = rowBase + wm + mi * 16 + g;
            int col  = colBase + wn + nj * 8 + tg * 2;
            float b0 = bias[col], b1 = bias[col + 1];
            float2 v0, v1;
            if (MODE == 1) {
                v0.x = to_tf32((c[mi][nj][0] + b0) * scale);
                v0.y = to_tf32((c[mi][nj][1] + b1) * scale);
                v1.x = to_tf32((c[mi][nj][2] + b0) * scale);
                v1.y = to_tf32((c[mi][nj][3] + b1) * scale);
            } else {
                v0.x = c[mi][nj][0] + b0; v0.y = c[mi][nj][1] + b1;
                v1.x = c[mi][nj][2] + b0; v1.y = c[mi][nj][3] + b1;
            }
            *(float2*)(C + (size_t)row0 * N + col)       = v0;
            *(float2*)(C + (size_t)(row0 + 8) * N + col) = v1;
        }
    }
#undef GEMM_STAGE
}

// ---------------------------------------------------------------------------
// TF32 flash attention, double-buffered K/V with prefetch-at-top.
// One block = (b,h) x 128 q-rows, 256 thr (8 warps), warp owns 16 S rows.
// Q fragments live in registers. smem 104448 B -> 2 CTAs/SM.
// ---------------------------------------------------------------------------
#define FS 68
__global__ void __launch_bounds__(256, 2) flash_tf32_kernel(
    const float* __restrict__ qkv, float* __restrict__ outp)
{
    extern __shared__ float sm[];
    float* Kb0 = sm;                     // 64*FS
    float* Vb0 = Kb0 + 64 * FS;
    float* Kb1 = Vb0 + 64 * FS;
    float* Vb1 = Kb1 + 64 * FS;
    float* Ps  = Vb1 + 64 * FS;          // 128*FS
    const uint32_t sK0 = (uint32_t)__cvta_generic_to_shared(Kb0);
    const uint32_t sP  = (uint32_t)__cvta_generic_to_shared(Ps);
    const uint32_t KVSTRIDE = (uint32_t)(2 * 64 * FS) * 4u;

    const int tid  = threadIdx.x;
    const int wid  = tid >> 5;
    const int lane = tid & 31;
    const int g    = lane >> 2;
    const int tg   = lane & 3;
    const int wrow = wid * 16;

    const int bh = blockIdx.y;
    const int b  = bh >> 4;
    const int h  = bh & 15;
    const int q0 = blockIdx.x * 128;

    const size_t rstride = (size_t)B_DIM * ROW3E;  // 24576

    // ldmatrix lane address components
    const int arow = (lane & 15);
    const int acol = (lane & 16) >> 2;
    const int bm   = lane >> 3;
    const int brow = ((bm >> 1) << 3) + (lane & 7);
    const int bcol = (bm & 1) << 2;

    // K/V tile loader: rows r0+p*16, chunk c4
    const int r0 = tid >> 4;
    const int c4 = (tid & 15) * 4;
    const float* kbase0 = qkv + (size_t)b * ROW3E + E_DIM + h * HD;

#define KV_STAGE(kt, buf)                                                     \
    {                                                                         \
        uint32_t sKb_ = sK0 + (buf) * KVSTRIDE;                               \
        uint32_t sVb_ = sKb_ + (uint32_t)(64 * FS) * 4u;                      \
        _Pragma("unroll")                                                     \
        for (int p = 0; p < 4; p++) {                                         \
            int rr_ = r0 + p * 16;                                            \
            const float* kb_ = kbase0 + (size_t)((kt) * 64 + rr_) * rstride + c4; \
            cp16(sKb_ + (uint32_t)((rr_ * FS + c4) * 4), kb_);                \
            cp16(sVb_ + (uint32_t)((rr_ * FS + c4) * 4), kb_ + E_DIM);        \
        }                                                                     \
        cp_commit();                                                          \
    }

    // ---- stage Q (pre-scaled tf32) into Ps, and KV tile 0 ----
    {
        const float* qbase = qkv + (size_t)(q0 * B_DIM + b) * ROW3E + h * HD;
#pragma unroll
        for (int p = 0; p < 8; p++) {
            int f4 = tid + p * 256;
            int r  = f4 >> 4;
            int cc = (f4 & 15) * 4;
            cp16(sP + (uint32_t)((r * FS + cc) * 4),
                 qbase + (size_t)r * rstride + cc);
        }
    }
    KV_STAGE(0, 0);
    cp_wait0();
    __syncthreads();

    // ---- Q fragments into registers ----
    uint32_t qa[8][4];
#pragma unroll
    for (int ks = 0; ks < 8; ks++)
        ldm_x4(qa[ks], sP + (uint32_t)((((wrow + arow) * FS) + ks * 8 + acol) * 4));
    __syncwarp();

    float o[8][4];
#pragma unroll
    for (int nj = 0; nj < 8; nj++)
#pragma unroll
        for (int r = 0; r < 4; r++) o[nj][r] = 0.f;
    float m0 = -1e30f, m1 = -1e30f, l0 = 0.f, l1 = 0.f;

    for (int kt = 0; kt < 16; kt++) {
        const int cur = kt & 1;
        if (kt + 1 < 16) KV_STAGE(kt + 1, 1 - cur);

        const uint32_t sKc = sK0 + cur * KVSTRIDE;
        const float* Vs = (cur ? Vb1 : Vb0);

        // ---- S = Q K^T ----
        float s[8][4];
#pragma unroll
        for (int nj = 0; nj < 8; nj++)
#pragma unroll
            for (int r = 0; r < 4; r++) s[nj][r] = 0.f;

#pragma unroll
        for (int ks = 0; ks < 8; ks++) {
            const int kk = ks * 8;
            uint32_t kb[8][2];
#pragma unroll
            for (int njp = 0; njp < 4; njp++)
                ldm_x4(&kb[njp * 2][0],
                       sKc + (uint32_t)((((njp * 16 + brow) * FS) + kk + bcol) * 4));
#pragma unroll
            for (int nj = 0; nj < 8; nj++)
                mma_tf32(s[nj], qa[ks], kb[nj]);
        }

        // ---- online softmax ----
        float rmax0 = -1e30f, rmax1 = -1e30f;
#pragma unroll
        for (int nj = 0; nj < 8; nj++) {
            rmax0 = fmaxf(rmax0, fmaxf(s[nj][0], s[nj][1]));
            rmax1 = fmaxf(rmax1, fmaxf(s[nj][2], s[nj][3]));
        }
        rmax0 = fmaxf(rmax0, __shfl_xor_sync(0xffffffffu, rmax0, 1));
        rmax0 = fmaxf(rmax0, __shfl_xor_sync(0xffffffffu, rmax0, 2));
        rmax1 = fmaxf(rmax1, __shfl_xor_sync(0xffffffffu, rmax1, 1));
        rmax1 = fmaxf(rmax1, __shfl_xor_sync(0xffffffffu, rmax1, 2));

        float nm0 = fmaxf(m0, rmax0), nm1 = fmaxf(m1, rmax1);
        float al0 = __expf(m0 - nm0), al1 = __expf(m1 - nm1);
        float rs0 = 0.f, rs1 = 0.f;
#pragma unroll
        for (int nj = 0; nj < 8; nj++) {
            s[nj][0] = __expf(s[nj][0] - nm0);
            s[nj][1] = __expf(s[nj][1] - nm0);
            s[nj][2] = __expf(s[nj][2] - nm1);
            s[nj][3] = __expf(s[nj][3] - nm1);
            rs0 += s[nj][0] + s[nj][1];
            rs1 += s[nj][2] + s[nj][3];
        }
        rs0 += __shfl_xor_sync(0xffffffffu, rs0, 1);
        rs0 += __shfl_xor_sync(0xffffffffu, rs0, 2);
        rs1 += __shfl_xor_sync(0xffffffffu, rs1, 1);
        rs1 += __shfl_xor_sync(0xffffffffu, rs1, 2);
        l0 = l0 * al0 + rs0;  m0 = nm0;
        l1 = l1 * al1 + rs1;  m1 = nm1;

#pragma unroll
        for (int nj = 0; nj < 8; nj++) {
            o[nj][0] *= al0; o[nj][1] *= al0;
            o[nj][2] *= al1; o[nj][3] *= al1;
        }

        // ---- write P (tf32) to warp-private smem rows ----
#pragma unroll
        for (int nj = 0; nj < 8; nj++) {
            int col = nj * 8 + tg * 2;
            float2 p0 = make_float2(to_tf32(s[nj][0]), to_tf32(s[nj][1]));
            float2 p1 = make_float2(to_tf32(s[nj][2]), to_tf32(s[nj][3]));
            *(float2*)&Ps[(wrow + g    ) * FS + col] = p0;
            *(float2*)&Ps[(wrow + g + 8) * FS + col] = p1;
        }
        __syncwarp();

        // ---- O += P @ V ----
#pragma unroll
        for (int ks = 0; ks < 8; ks++) {
            const int kk = ks * 8;
            uint32_t pa[4];
            ldm_x4(pa, sP + (uint32_t)((((wrow + arow) * FS) + kk + acol) * 4));
            uint32_t vb[8][2];
#pragma unroll
            for (int nj = 0; nj < 8; nj++) {
                int d = nj * 8 + g;
                vb[nj][0] = __float_as_uint(Vs[(kk + tg    ) * FS + d]);
                vb[nj][1] = __float_as_uint(Vs[(kk + tg + 4) * FS + d]);
            }
#pragma unroll
            for (int nj = 0; nj < 8; nj++)
                mma_tf32(o[nj], pa, vb[nj]);
        }

        cp_wait0();       // next tile's K/V resident
        __syncthreads();  // all warps done with cur buffers
    }

    // ---- epilogue ----
    float inv0 = 1.0f / l0, inv1 = 1.0f / l1;
#pragma unroll
    for (int nj = 0; nj < 8; nj++) {
        int col = h * HD + nj * 8 + tg * 2;
        int rr = q0 + wrow + g;
        float2 v0 = make_float2(to_tf32(o[nj][0] * inv0), to_tf32(o[nj][1] * inv0));
        float2 v1 = make_float2(to_tf32(o[nj][2] * inv1), to_tf32(o[nj][3] * inv1));
        *(float2*)(outp + (size_t)(rr * B_DIM + b) * E_DIM + col)       = v0;
        *(float2*)(outp + (size_t)((rr + 8) * B_DIM + b) * E_DIM + col) = v1;
    }
#undef KV_STAGE
}

// ---------------------------------------------------------------------------
// Launch
// ---------------------------------------------------------------------------
extern "C" void kernel_launch(void* const* d_in, const int* in_sizes, int n_in,
                              void* d_out, int out_size)
{
    const float* x    = (const float*)d_in[0];
    const float* wqkv = (const float*)d_in[1];
    const float* bqkv = (const float*)d_in[2];
    const float* wout = (const float*)d_in[3];
    const float* bout = (const float*)d_in[4];
    float* out = (float*)d_out;

    float *qkv, *attn, *xr, *wqkvr, *woutr;
    cudaGetSymbolAddress((void**)&qkv,   g_qkv);
    cudaGetSymbolAddress((void**)&attn,  g_attn);
    cudaGetSymbolAddress((void**)&xr,    g_xr);
    cudaGetSymbolAddress((void**)&wqkvr, g_wqkvr);
    cudaGetSymbolAddress((void**)&woutr, g_woutr);

    const size_t GEMM_SMEM  = (size_t)3 * 2 * 128 * GS * sizeof(float);  // 110592
    const size_t FLASH_SMEM = (size_t)(384 * FS) * sizeof(float);        // 104448
    cudaFuncSetAttribute(gemm_tf32_kernel<1>,
                         cudaFuncAttributeMaxDynamicSharedMemorySize, (int)GEMM_SMEM);
    cudaFuncSetAttribute(gemm_tf32_kernel<0>,
                         cudaFuncAttributeMaxDynamicSharedMemorySize, (int)GEMM_SMEM);
    cudaFuncSetAttribute(flash_tf32_kernel,
                         cudaFuncAttributeMaxDynamicSharedMemorySize, (int)FLASH_SMEM);

    // 0) prepass: round inputs to tf32
    {
        int n4;
        n4 = M_ROWS * E_DIM / 4;
        round_tf32_kernel<<<(n4 + 255) / 256, 256>>>((const float4*)x, (float4*)xr, n4);
        n4 = QKV_N * E_DIM / 4;
        round_tf32_kernel<<<(n4 + 255) / 256, 256>>>((const float4*)wqkv, (float4*)wqkvr, n4);
        n4 = E_DIM * E_DIM / 4;
        round_tf32_kernel<<<(n4 + 255) / 256, 256>>>((const float4*)wout, (float4*)woutr, n4);
    }

    // 1) QKV projection (rounded output, Q pre-scaled)
    {
        dim3 grid(QKV_N / 128, M_ROWS / 128);
        gemm_tf32_kernel<1><<<grid, 256, GEMM_SMEM>>>(xr, wqkvr, bqkv, qkv,
                                                      M_ROWS, QKV_N, E_DIM);
    }
    // 2) Attention
    {
        dim3 grid(L_DIM / 128, B_DIM * H_DIM);
        flash_tf32_kernel<<<grid, 256, FLASH_SMEM>>>(qkv, attn);
    }
    // 3) Output projection (full fp32 output)
    {
        dim3 grid(E_DIM / 128, M_ROWS / 128);
        gemm_tf32_kernel<0><<<grid, 256, GEMM_SMEM>>>(attn, woutr, bout, out,
                                                      M_ROWS, E_DIM, E_DIM);
    }
}

// round 8
// speedup vs baseline: 1.4931x; 1.0128x over previous
#include <cuda_runtime.h>
#include <cuda_bf16.h>
#include <math.h>
#include <stdint.h>

// Problem constants
#define L_DIM 1024
#define B_DIM 8
#define E_DIM 1024
#define H_DIM 16
#define HD    64
#define M_ROWS (L_DIM * B_DIM)      // 8192
#define QKV_N  (3 * E_DIM)          // 3072
#define ROW3E  (3 * E_DIM)

// Scratch (allocation-free rule: __device__ globals)
__device__ float g_qkv[(size_t)M_ROWS * QKV_N];   // rounded tf32, Q pre-scaled by 0.125*log2e
__device__ float g_attn[(size_t)M_ROWS * E_DIM];  // rounded tf32
__device__ float g_xr[(size_t)M_ROWS * E_DIM];    // rounded x
__device__ float g_wqkvr[(size_t)QKV_N * E_DIM];  // rounded Wqkv
__device__ float g_woutr[(size_t)E_DIM * E_DIM];  // rounded Wout

__device__ __forceinline__ float to_tf32(float x) {
    float y;
    asm("cvt.rna.tf32.f32 %0, %1;" : "=f"(y) : "f"(x));
    return y;
}

__device__ __forceinline__ void mma_tf32(float* c, const uint32_t* a, const uint32_t* b) {
    asm volatile(
        "mma.sync.aligned.m16n8k8.row.col.f32.tf32.tf32.f32 "
        "{%0,%1,%2,%3}, {%4,%5,%6,%7}, {%8,%9}, {%0,%1,%2,%3};\n"
        : "+f"(c[0]), "+f"(c[1]), "+f"(c[2]), "+f"(c[3])
        : "r"(a[0]), "r"(a[1]), "r"(a[2]), "r"(a[3]),
          "r"(b[0]), "r"(b[1]));
}

__device__ __forceinline__ void cp16(uint32_t sdst, const void* gsrc) {
    asm volatile("cp.async.cg.shared.global [%0], [%1], 16;\n"
                 :: "r"(sdst), "l"(gsrc));
}
__device__ __forceinline__ void cp_commit() {
    asm volatile("cp.async.commit_group;\n" ::: "memory");
}
__device__ __forceinline__ void cp_wait0() {
    asm volatile("cp.async.wait_group 0;\n" ::: "memory");
}
__device__ __forceinline__ void cp_wait1() {
    asm volatile("cp.async.wait_group 1;\n" ::: "memory");
}

__device__ __forceinline__ void ldm_x4(uint32_t* r, uint32_t addr) {
    asm volatile("ldmatrix.sync.aligned.m8n8.x4.shared.b16 {%0,%1,%2,%3}, [%4];"
        : "=r"(r[0]), "=r"(r[1]), "=r"(r[2]), "=r"(r[3]) : "r"(addr));
}

// ---------------------------------------------------------------------------
// Fused prepass: round x, Wqkv, Wout to tf32 in one launch
// ---------------------------------------------------------------------------
#define NX4  (M_ROWS * E_DIM / 4)          // 2097152
#define NW14 (QKV_N * E_DIM / 4)           // 786432
#define NW24 (E_DIM * E_DIM / 4)           // 262144

__global__ void round_all_kernel(const float4* __restrict__ x,   float4* __restrict__ xr,
                                 const float4* __restrict__ wq,  float4* __restrict__ wqr,
                                 const float4* __restrict__ wo,  float4* __restrict__ wor)
{
    int i = blockIdx.x * blockDim.x + threadIdx.x;
    const float4* src; float4* dst; int j;
    if (i < NX4)               { src = x;  dst = xr;  j = i; }
    else if (i < NX4 + NW14)   { src = wq; dst = wqr; j = i - NX4; }
    else if (i < NX4 + NW14 + NW24) { src = wo; dst = wor; j = i - NX4 - NW14; }
    else return;
    float4 v = src[j];
    v.x = to_tf32(v.x); v.y = to_tf32(v.y);
    v.z = to_tf32(v.z); v.w = to_tf32(v.w);
    dst[j] = v;
}

// ---------------------------------------------------------------------------
// TF32 GEMM: C[M,N] = A[M,K] @ W[N,K]^T + bias[N]
// 256 threads = 8 warps (2x4 grid of 64x32 warp tiles), block tile 128x128,
// K-tile 32, 3-stage cp.async pipeline, ldmatrix fragments, 2 CTAs/SM.
// MODE 0: plain fp32 out.
// MODE 1: qkv out (round; scale Q columns by 0.125*log2e for exp2-domain softmax).
// ---------------------------------------------------------------------------
#define GS 36
#define QSCALE (0.125f * 1.44269504088896340736f)

template<int MODE>
__global__ void __launch_bounds__(256, 2) gemm_tf32_kernel(
    const float* __restrict__ A, const float* __restrict__ W,
    const float* __restrict__ bias, float* __restrict__ C,
    int M, int N, int K)
{
    extern __shared__ float smg[];
    const int STAGEF = 2 * 128 * GS;   // floats per stage (A tile + W tile)
    const uint32_t sbase = (uint32_t)__cvta_generic_to_shared(smg);

    const int tid  = threadIdx.x;
    const int lane = tid & 31;
    const int wid  = tid >> 5;
    const int wm   = (wid >> 2) * 64;
    const int wn   = (wid & 3) * 32;
    const int rowBase = blockIdx.y * 128;
    const int colBase = blockIdx.x * 128;

    // cp.async loader mapping: rows r0+32p, 16B chunk c4
    const int r0 = tid >> 3;
    const int c4 = (tid & 7) * 4;
    const float* Aptr = A + (size_t)(rowBase + r0) * K + c4;
    const float* Wptr = W + (size_t)(colBase + r0) * K + c4;

    // ldmatrix per-lane address components
    const int arow = (lane & 15);
    const int acol = (lane & 16) >> 2;
    const int bm   = lane >> 3;           // B: x4 over 16 rows x 8 k
    const int brow = ((bm >> 1) << 3) + (lane & 7);
    const int bcol = (bm & 1) << 2;

    float c[4][4][4];
#pragma unroll
    for (int mi = 0; mi < 4; mi++)
#pragma unroll
        for (int nj = 0; nj < 4; nj++)
#pragma unroll
            for (int r = 0; r < 4; r++) c[mi][nj][r] = 0.f;

#define GEMM_STAGE(buf, k0)                                                    \
    {                                                                          \
        uint32_t sb_ = sbase + (uint32_t)((buf) * STAGEF) * 4u;                \
        _Pragma("unroll")                                                      \
        for (int p = 0; p < 4; p++) {                                          \
            cp16(sb_ + (uint32_t)(((r0 + p * 32) * GS + c4) * 4),              \
                 Aptr + (size_t)(p * 32) * K + (k0));                          \
            cp16(sb_ + (uint32_t)((128 * GS + (r0 + p * 32) * GS + c4) * 4),   \
                 Wptr + (size_t)(p * 32) * K + (k0));                          \
        }                                                                      \
        cp_commit();                                                           \
    }

    const int T = K >> 5;
    GEMM_STAGE(0, 0);
    GEMM_STAGE(1, 32);

    int cbuf = 0;
    for (int t = 0; t < T; t++) {
        if (t == T - 1) cp_wait0(); else cp_wait1();
        __syncthreads();

        if (t + 2 < T) {
            int nb = cbuf + 2; if (nb >= 3) nb -= 3;
            GEMM_STAGE(nb, (t + 2) << 5);
        }

        const uint32_t Ab = sbase + (uint32_t)(cbuf * STAGEF) * 4u;
        const uint32_t Wb = Ab + (uint32_t)(128 * GS) * 4u;
#pragma unroll
        for (int ks = 0; ks < 4; ks++) {
            const int kk = ks * 8;
            uint32_t a[4][4], b[4][2];
#pragma unroll
            for (int mi = 0; mi < 4; mi++)
                ldm_x4(a[mi], Ab + (uint32_t)((((wm + mi * 16 + arow) * GS) + kk + acol) * 4));
#pragma unroll
            for (int njp = 0; njp < 2; njp++)
                ldm_x4(&b[njp * 2][0],
                       Wb + (uint32_t)((((wn + njp * 16 + brow) * GS) + kk + bcol) * 4));
#pragma unroll
            for (int mi = 0; mi < 4; mi++)
#pragma unroll
                for (int nj = 0; nj < 4; nj++)
                    mma_tf32(c[mi][nj], a[mi], b[nj]);
        }
        cbuf++; if (cbuf == 3) cbuf = 0;
    }

    // epilogue
    const int g  = lane >> 2;
    const int tg = lane & 3;
    float scale = 1.f;
    if (MODE == 1) scale = (colBase < E_DIM) ? QSCALE : 1.f;
#pragma unroll
    for (int mi = 0; mi < 4; mi++) {
#pragma unroll
        for (int nj = 0; nj < 4; nj++) {
            int row0 = rowBase + wm + mi * 16 + g;
            int col  = colBase + wn + nj * 8 + tg * 2;
            float b0 = bias[col], b1 = bias[col + 1];
            float2 v0, v1;
            if (MODE == 1) {
                v0.x = to_tf32((c[mi][nj][0] + b0) * scale);
                v0.y = to_tf32((c[mi][nj][1] + b1) * scale);
                v1.x = to_tf32((c[mi][nj][2] + b0) * scale);
                v1.y = to_tf32((c[mi][nj][3] + b1) * scale);
            } else {
                v0.x = c[mi][nj][0] + b0; v0.y = c[mi][nj][1] + b1;
                v1.x = c[mi][nj][2] + b0; v1.y = c[mi][nj][3] + b1;
            }
            *(float2*)(C + (size_t)row0 * N + col)       = v0;
            *(float2*)(C + (size_t)(row0 + 8) * N + col) = v1;
        }
    }
#undef GEMM_STAGE
}

// ---------------------------------------------------------------------------
// TF32 flash attention, double-buffered K/V with prefetch-at-top.
// Softmax in exp2 domain (Q pre-scaled by 0.125*log2e in the QKV epilogue).
// One block = (b,h) x 128 q-rows, 256 thr (8 warps), warp owns 16 S rows.
// Q fragments live in registers. smem 104448 B -> 2 CTAs/SM.
// ---------------------------------------------------------------------------
#define FS 68
__global__ void __launch_bounds__(256, 2) flash_tf32_kernel(
    const float* __restrict__ qkv, float* __restrict__ outp)
{
    extern __shared__ float sm[];
    float* Kb0 = sm;
    float* Vb0 = Kb0 + 64 * FS;
    float* Kb1 = Vb0 + 64 * FS;
    float* Vb1 = Kb1 + 64 * FS;
    float* Ps  = Vb1 + 64 * FS;
    const uint32_t sK0 = (uint32_t)__cvta_generic_to_shared(Kb0);
    const uint32_t sP  = (uint32_t)__cvta_generic_to_shared(Ps);
    const uint32_t KVSTRIDE = (uint32_t)(2 * 64 * FS) * 4u;

    const int tid  = threadIdx.x;
    const int wid  = tid >> 5;
    const int lane = tid & 31;
    const int g    = lane >> 2;
    const int tg   = lane & 3;
    const int wrow = wid * 16;

    const int bh = blockIdx.y;
    const int b  = bh >> 4;
    const int h  = bh & 15;
    const int q0 = blockIdx.x * 128;

    const size_t rstride = (size_t)B_DIM * ROW3E;

    const int arow = (lane & 15);
    const int acol = (lane & 16) >> 2;
    const int bm   = lane >> 3;
    const int brow = ((bm >> 1) << 3) + (lane & 7);
    const int bcol = (bm & 1) << 2;

    const int r0 = tid >> 4;
    const int c4 = (tid & 15) * 4;
    const float* kbase0 = qkv + (size_t)b * ROW3E + E_DIM + h * HD;

#define KV_STAGE(kt, buf)                                                     \
    {                                                                         \
        uint32_t sKb_ = sK0 + (buf) * KVSTRIDE;                               \
        uint32_t sVb_ = sKb_ + (uint32_t)(64 * FS) * 4u;                      \
        _Pragma("unroll")                                                     \
        for (int p = 0; p < 4; p++) {                                         \
            int rr_ = r0 + p * 16;                                            \
            const float* kb_ = kbase0 + (size_t)((kt) * 64 + rr_) * rstride + c4; \
            cp16(sKb_ + (uint32_t)((rr_ * FS + c4) * 4), kb_);                \
            cp16(sVb_ + (uint32_t)((rr_ * FS + c4) * 4), kb_ + E_DIM);        \
        }                                                                     \
        cp_commit();                                                          \
    }

    {
        const float* qbase = qkv + (size_t)(q0 * B_DIM + b) * ROW3E + h * HD;
#pragma unroll
        for (int p = 0; p < 8; p++) {
            int f4 = tid + p * 256;
            int r  = f4 >> 4;
            int cc = (f4 & 15) * 4;
            cp16(sP + (uint32_t)((r * FS + cc) * 4),
                 qbase + (size_t)r * rstride + cc);
        }
    }
    KV_STAGE(0, 0);
    cp_wait0();
    __syncthreads();

    uint32_t qa[8][4];
#pragma unroll
    for (int ks = 0; ks < 8; ks++)
        ldm_x4(qa[ks], sP + (uint32_t)((((wrow + arow) * FS) + ks * 8 + acol) * 4));
    __syncwarp();

    float o[8][4];
#pragma unroll
    for (int nj = 0; nj < 8; nj++)
#pragma unroll
        for (int r = 0; r < 4; r++) o[nj][r] = 0.f;
    float m0 = -1e30f, m1 = -1e30f, l0 = 0.f, l1 = 0.f;

    for (int kt = 0; kt < 16; kt++) {
        const int cur = kt & 1;
        if (kt + 1 < 16) KV_STAGE(kt + 1, 1 - cur);

        const uint32_t sKc = sK0 + cur * KVSTRIDE;
        const float* Vs = (cur ? Vb1 : Vb0);

        // ---- S = Q K^T (S is in log2-units) ----
        float s[8][4];
#pragma unroll
        for (int nj = 0; nj < 8; nj++)
#pragma unroll
            for (int r = 0; r < 4; r++) s[nj][r] = 0.f;

#pragma unroll
        for (int ks = 0; ks < 8; ks++) {
            const int kk = ks * 8;
            uint32_t kb[8][2];
#pragma unroll
            for (int njp = 0; njp < 4; njp++)
                ldm_x4(&kb[njp * 2][0],
                       sKc + (uint32_t)((((njp * 16 + brow) * FS) + kk + bcol) * 4));
#pragma unroll
            for (int nj = 0; nj < 8; nj++)
                mma_tf32(s[nj], qa[ks], kb[nj]);
        }

        // ---- online softmax, exp2 domain ----
        float rmax0 = -1e30f, rmax1 = -1e30f;
#pragma unroll
        for (int nj = 0; nj < 8; nj++) {
            rmax0 = fmaxf(rmax0, fmaxf(s[nj][0], s[nj][1]));
            rmax1 = fmaxf(rmax1, fmaxf(s[nj][2], s[nj][3]));
        }
        rmax0 = fmaxf(rmax0, __shfl_xor_sync(0xffffffffu, rmax0, 1));
        rmax0 = fmaxf(rmax0, __shfl_xor_sync(0xffffffffu, rmax0, 2));
        rmax1 = fmaxf(rmax1, __shfl_xor_sync(0xffffffffu, rmax1, 1));
        rmax1 = fmaxf(rmax1, __shfl_xor_sync(0xffffffffu, rmax1, 2));

        float nm0 = fmaxf(m0, rmax0), nm1 = fmaxf(m1, rmax1);
        float al0 = exp2f(m0 - nm0), al1 = exp2f(m1 - nm1);
        float rs0 = 0.f, rs1 = 0.f;
#pragma unroll
        for (int nj = 0; nj < 8; nj++) {
            s[nj][0] = exp2f(s[nj][0] - nm0);
            s[nj][1] = exp2f(s[nj][1] - nm0);
            s[nj][2] = exp2f(s[nj][2] - nm1);
            s[nj][3] = exp2f(s[nj][3] - nm1);
            rs0 += s[nj][0] + s[nj][1];
            rs1 += s[nj][2] + s[nj][3];
        }
        rs0 += __shfl_xor_sync(0xffffffffu, rs0, 1);
        rs0 += __shfl_xor_sync(0xffffffffu, rs0, 2);
        rs1 += __shfl_xor_sync(0xffffffffu, rs1, 1);
        rs1 += __shfl_xor_sync(0xffffffffu, rs1, 2);
        l0 = l0 * al0 + rs0;  m0 = nm0;
        l1 = l1 * al1 + rs1;  m1 = nm1;

#pragma unroll
        for (int nj = 0; nj < 8; nj++) {
            o[nj][0] *= al0; o[nj][1] *= al0;
            o[nj][2] *= al1; o[nj][3] *= al1;
        }

        // ---- write P (tf32) to warp-private smem rows ----
#pragma unroll
        for (int nj = 0; nj < 8; nj++) {
            int col = nj * 8 + tg * 2;
            float2 p0 = make_float2(to_tf32(s[nj][0]), to_tf32(s[nj][1]));
            float2 p1 = make_float2(to_tf32(s[nj][2]), to_tf32(s[nj][3]));
            *(float2*)&Ps[(wrow + g    ) * FS + col] = p0;
            *(float2*)&Ps[(wrow + g + 8) * FS + col] = p1;
        }
        __syncwarp();

        // ---- O += P @ V ----
#pragma unroll
        for (int ks = 0; ks < 8; ks++) {
            const int kk = ks * 8;
            uint32_t pa[4];
            ldm_x4(pa, sP + (uint32_t)((((wrow + arow) * FS) + kk + acol) * 4));
            uint32_t vb[8][2];
#pragma unroll
            for (int nj = 0; nj < 8; nj++) {
                int d = nj * 8 + g;
                vb[nj][0] = __float_as_uint(Vs[(kk + tg    ) * FS + d]);
                vb[nj][1] = __float_as_uint(Vs[(kk + tg + 4) * FS + d]);
            }
#pragma unroll
            for (int nj = 0; nj < 8; nj++)
                mma_tf32(o[nj], pa, vb[nj]);
        }

        cp_wait0();
        __syncthreads();
    }

    // ---- epilogue ----
    float inv0 = 1.0f / l0, inv1 = 1.0f / l1;
#pragma unroll
    for (int nj = 0; nj < 8; nj++) {
        int col = h * HD + nj * 8 + tg * 2;
        int rr = q0 + wrow + g;
        float2 v0 = make_float2(to_tf32(o[nj][0] * inv0), to_tf32(o[nj][1] * inv0));
        float2 v1 = make_float2(to_tf32(o[nj][2] * inv1), to_tf32(o[nj][3] * inv1));
        *(float2*)(outp + (size_t)(rr * B_DIM + b) * E_DIM + col)       = v0;
        *(float2*)(outp + (size_t)((rr + 8) * B_DIM + b) * E_DIM + col) = v1;
    }
#undef KV_STAGE
}

// ---------------------------------------------------------------------------
// Launch
// ---------------------------------------------------------------------------
extern "C" void kernel_launch(void* const* d_in, const int* in_sizes, int n_in,
                              void* d_out, int out_size)
{
    const float* x    = (const float*)d_in[0];
    const float* wqkv = (const float*)d_in[1];
    const float* bqkv = (const float*)d_in[2];
    const float* wout = (const float*)d_in[3];
    const float* bout = (const float*)d_in[4];
    float* out = (float*)d_out;

    float *qkv, *attn, *xr, *wqkvr, *woutr;
    cudaGetSymbolAddress((void**)&qkv,   g_qkv);
    cudaGetSymbolAddress((void**)&attn,  g_attn);
    cudaGetSymbolAddress((void**)&xr,    g_xr);
    cudaGetSymbolAddress((void**)&wqkvr, g_wqkvr);
    cudaGetSymbolAddress((void**)&woutr, g_woutr);

    const size_t GEMM_SMEM  = (size_t)3 * 2 * 128 * GS * sizeof(float);  // 110592
    const size_t FLASH_SMEM = (size_t)(384 * FS) * sizeof(float);        // 104448
    cudaFuncSetAttribute(gemm_tf32_kernel<1>,
                         cudaFuncAttributeMaxDynamicSharedMemorySize, (int)GEMM_SMEM);
    cudaFuncSetAttribute(gemm_tf32_kernel<0>,
                         cudaFuncAttributeMaxDynamicSharedMemorySize, (int)GEMM_SMEM);
    cudaFuncSetAttribute(flash_tf32_kernel,
                         cudaFuncAttributeMaxDynamicSharedMemorySize, (int)FLASH_SMEM);

    // 0) fused prepass: round inputs to tf32
    {
        int total = NX4 + NW14 + NW24;
        round_all_kernel<<<(total + 255) / 256, 256>>>(
            (const float4*)x, (float4*)xr,
            (const float4*)wqkv, (float4*)wqkvr,
            (const float4*)wout, (float4*)woutr);
    }

    // 1) QKV projection (rounded output, Q pre-scaled by 0.125*log2e)
    {
        dim3 grid(QKV_N / 128, M_ROWS / 128);
        gemm_tf32_kernel<1><<<grid, 256, GEMM_SMEM>>>(xr, wqkvr, bqkv, qkv,
                                                      M_ROWS, QKV_N, E_DIM);
    }
    // 2) Attention (exp2-domain softmax)
    {
        dim3 grid(L_DIM / 128, B_DIM * H_DIM);
        flash_tf32_kernel<<<grid, 256, FLASH_SMEM>>>(qkv, attn);
    }
    // 3) Output projection (full fp32 output)
    {
        dim3 grid(E_DIM / 128, M_ROWS / 128);
        gemm_tf32_kernel<0><<<grid, 256, GEMM_SMEM>>>(attn, woutr, bout, out,
                                                      M_ROWS, E_DIM, E_DIM);
    }
}

// round 9
// speedup vs baseline: 1.6292x; 1.0912x over previous
#include <cuda_runtime.h>
#include <cuda_bf16.h>
#include <math.h>
#include <stdint.h>

// Problem constants
#define L_DIM 1024
#define B_DIM 8
#define E_DIM 1024
#define H_DIM 16
#define HD    64
#define M_ROWS (L_DIM * B_DIM)      // 8192
#define QKV_N  (3 * E_DIM)          // 3072
#define ROW3E  (3 * E_DIM)

// Scratch (allocation-free rule: __device__ globals)
__device__ float g_qkv[(size_t)M_ROWS * QKV_N];   // rounded tf32, Q pre-scaled by 0.125*log2e
__device__ float g_attn[(size_t)M_ROWS * E_DIM];  // rounded tf32
__device__ float g_xr[(size_t)M_ROWS * E_DIM];    // rounded x
__device__ float g_wqkvr[(size_t)QKV_N * E_DIM];  // rounded Wqkv
__device__ float g_woutr[(size_t)E_DIM * E_DIM];  // rounded Wout

__device__ __forceinline__ float to_tf32(float x) {
    float y;
    asm("cvt.rna.tf32.f32 %0, %1;" : "=f"(y) : "f"(x));
    return y;
}

__device__ __forceinline__ void mma_tf32(float* c, const uint32_t* a, const uint32_t* b) {
    asm volatile(
        "mma.sync.aligned.m16n8k8.row.col.f32.tf32.tf32.f32 "
        "{%0,%1,%2,%3}, {%4,%5,%6,%7}, {%8,%9}, {%0,%1,%2,%3};\n"
        : "+f"(c[0]), "+f"(c[1]), "+f"(c[2]), "+f"(c[3])
        : "r"(a[0]), "r"(a[1]), "r"(a[2]), "r"(a[3]),
          "r"(b[0]), "r"(b[1]));
}

__device__ __forceinline__ void cp16(uint32_t sdst, const void* gsrc) {
    asm volatile("cp.async.cg.shared.global [%0], [%1], 16;\n"
                 :: "r"(sdst), "l"(gsrc));
}
__device__ __forceinline__ void cp_commit() {
    asm volatile("cp.async.commit_group;\n" ::: "memory");
}
__device__ __forceinline__ void cp_wait0() {
    asm volatile("cp.async.wait_group 0;\n" ::: "memory");
}
__device__ __forceinline__ void cp_wait1() {
    asm volatile("cp.async.wait_group 1;\n" ::: "memory");
}

__device__ __forceinline__ void ldm_x4(uint32_t* r, uint32_t addr) {
    asm volatile("ldmatrix.sync.aligned.m8n8.x4.shared.b16 {%0,%1,%2,%3}, [%4];"
        : "=r"(r[0]), "=r"(r[1]), "=r"(r[2]), "=r"(r[3]) : "r"(addr));
}

// ---------------------------------------------------------------------------
// Fused prepass: round x, Wqkv, Wout to tf32 in one launch
// ---------------------------------------------------------------------------
#define NX4  (M_ROWS * E_DIM / 4)          // 2097152
#define NW14 (QKV_N * E_DIM / 4)           // 786432
#define NW24 (E_DIM * E_DIM / 4)           // 262144

__global__ void round_all_kernel(const float4* __restrict__ x,   float4* __restrict__ xr,
                                 const float4* __restrict__ wq,  float4* __restrict__ wqr,
                                 const float4* __restrict__ wo,  float4* __restrict__ wor)
{
    int i = blockIdx.x * blockDim.x + threadIdx.x;
    const float4* src; float4* dst; int j;
    if (i < NX4)               { src = x;  dst = xr;  j = i; }
    else if (i < NX4 + NW14)   { src = wq; dst = wqr; j = i - NX4; }
    else if (i < NX4 + NW14 + NW24) { src = wo; dst = wor; j = i - NX4 - NW14; }
    else return;
    float4 v = src[j];
    v.x = to_tf32(v.x); v.y = to_tf32(v.y);
    v.z = to_tf32(v.z); v.w = to_tf32(v.w);
    dst[j] = v;
}

// ---------------------------------------------------------------------------
// TF32 GEMM: C[M,N] = A[M,K] @ W[N,K]^T + bias[N]
// 256 threads = 8 warps (2x4 grid of 64x32 warp tiles), block tile 128x128,
// K-tile 32, 3-stage cp.async pipeline, ldmatrix fragments, 2 CTAs/SM.
// MODE 0: plain fp32 out.
// MODE 1: qkv out (round; scale Q columns by 0.125*log2e for exp2-domain softmax).
// ---------------------------------------------------------------------------
#define GS 36
#define QSCALE (0.125f * 1.44269504088896340736f)

template<int MODE>
__global__ void __launch_bounds__(256, 2) gemm_tf32_kernel(
    const float* __restrict__ A, const float* __restrict__ W,
    const float* __restrict__ bias, float* __restrict__ C,
    int M, int N, int K)
{
    extern __shared__ float smg[];
    const int STAGEF = 2 * 128 * GS;   // floats per stage (A tile + W tile)
    const uint32_t sbase = (uint32_t)__cvta_generic_to_shared(smg);

    const int tid  = threadIdx.x;
    const int lane = tid & 31;
    const int wid  = tid >> 5;
    const int wm   = (wid >> 2) * 64;
    const int wn   = (wid & 3) * 32;
    const int rowBase = blockIdx.y * 128;
    const int colBase = blockIdx.x * 128;

    // cp.async loader mapping: rows r0+32p, 16B chunk c4
    const int r0 = tid >> 3;
    const int c4 = (tid & 7) * 4;
    const float* Aptr = A + (size_t)(rowBase + r0) * K + c4;
    const float* Wptr = W + (size_t)(colBase + r0) * K + c4;

    // ldmatrix per-lane address components
    const int arow = (lane & 15);
    const int acol = (lane & 16) >> 2;
    const int bm   = lane >> 3;           // B: x4 over 16 rows x 8 k
    const int brow = ((bm >> 1) << 3) + (lane & 7);
    const int bcol = (bm & 1) << 2;

    float c[4][4][4];
#pragma unroll
    for (int mi = 0; mi < 4; mi++)
#pragma unroll
        for (int nj = 0; nj < 4; nj++)
#pragma unroll
            for (int r = 0; r < 4; r++) c[mi][nj][r] = 0.f;

#define GEMM_STAGE(buf, k0)                                                    \
    {                                                                          \
        uint32_t sb_ = sbase + (uint32_t)((buf) * STAGEF) * 4u;                \
        _Pragma("unroll")                                                      \
        for (int p = 0; p < 4; p++) {                                          \
            cp16(sb_ + (uint32_t)(((r0 + p * 32) * GS + c4) * 4),              \
                 Aptr + (size_t)(p * 32) * K + (k0));                          \
            cp16(sb_ + (uint32_t)((128 * GS + (r0 + p * 32) * GS + c4) * 4),   \
                 Wptr + (size_t)(p * 32) * K + (k0));                          \
        }                                                                      \
        cp_commit();                                                           \
    }

    const int T = K >> 5;
    GEMM_STAGE(0, 0);
    GEMM_STAGE(1, 32);

    int cbuf = 0;
    for (int t = 0; t < T; t++) {
        if (t == T - 1) cp_wait0(); else cp_wait1();
        __syncthreads();

        if (t + 2 < T) {
            int nb = cbuf + 2; if (nb >= 3) nb -= 3;
            GEMM_STAGE(nb, (t + 2) << 5);
        }

        const uint32_t Ab = sbase + (uint32_t)(cbuf * STAGEF) * 4u;
        const uint32_t Wb = Ab + (uint32_t)(128 * GS) * 4u;
#pragma unroll
        for (int ks = 0; ks < 4; ks++) {
            const int kk = ks * 8;
            uint32_t a[4][4], b[4][2];
#pragma unroll
            for (int mi = 0; mi < 4; mi++)
                ldm_x4(a[mi], Ab + (uint32_t)((((wm + mi * 16 + arow) * GS) + kk + acol) * 4));
#pragma unroll
            for (int njp = 0; njp < 2; njp++)
                ldm_x4(&b[njp * 2][0],
                       Wb + (uint32_t)((((wn + njp * 16 + brow) * GS) + kk + bcol) * 4));
#pragma unroll
            for (int mi = 0; mi < 4; mi++)
#pragma unroll
                for (int nj = 0; nj < 4; nj++)
                    mma_tf32(c[mi][nj], a[mi], b[nj]);
        }
        cbuf++; if (cbuf == 3) cbuf = 0;
    }

    // epilogue
    const int g  = lane >> 2;
    const int tg = lane & 3;
    float scale = 1.f;
    if (MODE == 1) scale = (colBase < E_DIM) ? QSCALE : 1.f;
#pragma unroll
    for (int mi = 0; mi < 4; mi++) {
#pragma unroll
        for (int nj = 0; nj < 4; nj++) {
            int row0 = rowBase + wm + mi * 16 + g;
            int col  = colBase + wn + nj * 8 + tg * 2;
            float b0 = bias[col], b1 = bias[col + 1];
            float2 v0, v1;
            if (MODE == 1) {
                v0.x = to_tf32((c[mi][nj][0] + b0) * scale);
                v0.y = to_tf32((c[mi][nj][1] + b1) * scale);
                v1.x = to_tf32((c[mi][nj][2] + b0) * scale);
                v1.y = to_tf32((c[mi][nj][3] + b1) * scale);
            } else {
                v0.x = c[mi][nj][0] + b0; v0.y = c[mi][nj][1] + b1;
                v1.x = c[mi][nj][2] + b0; v1.y = c[mi][nj][3] + b1;
            }
            *(float2*)(C + (size_t)row0 * N + col)       = v0;
            *(float2*)(C + (size_t)(row0 + 8) * N + col) = v1;
        }
    }
#undef GEMM_STAGE
}

// ---------------------------------------------------------------------------
// TF32 flash attention, double-buffered K/V with prefetch-at-top.
// Softmax in exp2 domain (Q pre-scaled by 0.125*log2e in the QKV epilogue).
// One block = (b,h) x 128 q-rows, 256 thr (8 warps), warp owns 16 S rows.
// Q fragments live in registers.
// V uses a dedicated smem stride of 72 floats: lane bank = (8*tg + 8*nj + g)
// mod 32 covers all 32 banks -> fully conflict-free scalar V-fragment loads
// (stride 68 had a 2-way conflict between tg quads).
// smem: K 2x64x68 + V 2x64x72 + Ps 128x68 = 106496 B -> 2 CTAs/SM.
// ---------------------------------------------------------------------------
#define FS 68
#define VS 72
__global__ void __launch_bounds__(256, 2) flash_tf32_kernel(
    const float* __restrict__ qkv, float* __restrict__ outp)
{
    extern __shared__ float sm[];
    float* Kb0 = sm;                       // 64*FS
    float* Kb1 = Kb0 + 64 * FS;            // 64*FS
    float* Vb0 = Kb1 + 64 * FS;            // 64*VS
    float* Vb1 = Vb0 + 64 * VS;            // 64*VS
    float* Ps  = Vb1 + 64 * VS;            // 128*FS
    const uint32_t sK0 = (uint32_t)__cvta_generic_to_shared(Kb0);
    const uint32_t sV0 = (uint32_t)__cvta_generic_to_shared(Vb0);
    const uint32_t sP  = (uint32_t)__cvta_generic_to_shared(Ps);
    const uint32_t KBUF = (uint32_t)(64 * FS) * 4u;
    const uint32_t VBUF = (uint32_t)(64 * VS) * 4u;

    const int tid  = threadIdx.x;
    const int wid  = tid >> 5;
    const int lane = tid & 31;
    const int g    = lane >> 2;
    const int tg   = lane & 3;
    const int wrow = wid * 16;

    const int bh = blockIdx.y;
    const int b  = bh >> 4;
    const int h  = bh & 15;
    const int q0 = blockIdx.x * 128;

    const size_t rstride = (size_t)B_DIM * ROW3E;

    const int arow = (lane & 15);
    const int acol = (lane & 16) >> 2;
    const int bm   = lane >> 3;
    const int brow = ((bm >> 1) << 3) + (lane & 7);
    const int bcol = (bm & 1) << 2;

    const int r0 = tid >> 4;
    const int c4 = (tid & 15) * 4;
    const float* kbase0 = qkv + (size_t)b * ROW3E + E_DIM + h * HD;

#define KV_STAGE(kt, buf)                                                     \
    {                                                                         \
        uint32_t sKb_ = sK0 + (buf) * KBUF;                                   \
        uint32_t sVb_ = sV0 + (buf) * VBUF;                                   \
        _Pragma("unroll")                                                     \
        for (int p = 0; p < 4; p++) {                                         \
            int rr_ = r0 + p * 16;                                            \
            const float* kb_ = kbase0 + (size_t)((kt) * 64 + rr_) * rstride + c4; \
            cp16(sKb_ + (uint32_t)((rr_ * FS + c4) * 4), kb_);                \
            cp16(sVb_ + (uint32_t)((rr_ * VS + c4) * 4), kb_ + E_DIM);        \
        }                                                                     \
        cp_commit();                                                          \
    }

    {
        const float* qbase = qkv + (size_t)(q0 * B_DIM + b) * ROW3E + h * HD;
#pragma unroll
        for (int p = 0; p < 8; p++) {
            int f4 = tid + p * 256;
            int r  = f4 >> 4;
            int cc = (f4 & 15) * 4;
            cp16(sP + (uint32_t)((r * FS + cc) * 4),
                 qbase + (size_t)r * rstride + cc);
        }
    }
    KV_STAGE(0, 0);
    cp_wait0();
    __syncthreads();

    uint32_t qa[8][4];
#pragma unroll
    for (int ks = 0; ks < 8; ks++)
        ldm_x4(qa[ks], sP + (uint32_t)((((wrow + arow) * FS) + ks * 8 + acol) * 4));
    __syncwarp();

    float o[8][4];
#pragma unroll
    for (int nj = 0; nj < 8; nj++)
#pragma unroll
        for (int r = 0; r < 4; r++) o[nj][r] = 0.f;
    float m0 = -1e30f, m1 = -1e30f, l0 = 0.f, l1 = 0.f;

    for (int kt = 0; kt < 16; kt++) {
        const int cur = kt & 1;
        if (kt + 1 < 16) KV_STAGE(kt + 1, 1 - cur);

        const uint32_t sKc = sK0 + cur * KBUF;
        const float* Vs = (cur ? Vb1 : Vb0);

        // ---- S = Q K^T (S is in log2-units) ----
        float s[8][4];
#pragma unroll
        for (int nj = 0; nj < 8; nj++)
#pragma unroll
            for (int r = 0; r < 4; r++) s[nj][r] = 0.f;

#pragma unroll
        for (int ks = 0; ks < 8; ks++) {
            const int kk = ks * 8;
            uint32_t kb[8][2];
#pragma unroll
            for (int njp = 0; njp < 4; njp++)
                ldm_x4(&kb[njp * 2][0],
                       sKc + (uint32_t)((((njp * 16 + brow) * FS) + kk + bcol) * 4));
#pragma unroll
            for (int nj = 0; nj < 8; nj++)
                mma_tf32(s[nj], qa[ks], kb[nj]);
        }

        // ---- online softmax, exp2 domain ----
        float rmax0 = -1e30f, rmax1 = -1e30f;
#pragma unroll
        for (int nj = 0; nj < 8; nj++) {
            rmax0 = fmaxf(rmax0, fmaxf(s[nj][0], s[nj][1]));
            rmax1 = fmaxf(rmax1, fmaxf(s[nj][2], s[nj][3]));
        }
        rmax0 = fmaxf(rmax0, __shfl_xor_sync(0xffffffffu, rmax0, 1));
        rmax0 = fmaxf(rmax0, __shfl_xor_sync(0xffffffffu, rmax0, 2));
        rmax1 = fmaxf(rmax1, __shfl_xor_sync(0xffffffffu, rmax1, 1));
        rmax1 = fmaxf(rmax1, __shfl_xor_sync(0xffffffffu, rmax1, 2));

        float nm0 = fmaxf(m0, rmax0), nm1 = fmaxf(m1, rmax1);
        float al0 = exp2f(m0 - nm0), al1 = exp2f(m1 - nm1);
        float rs0 = 0.f, rs1 = 0.f;
#pragma unroll
        for (int nj = 0; nj < 8; nj++) {
            s[nj][0] = exp2f(s[nj][0] - nm0);
            s[nj][1] = exp2f(s[nj][1] - nm0);
            s[nj][2] = exp2f(s[nj][2] - nm1);
            s[nj][3] = exp2f(s[nj][3] - nm1);
            rs0 += s[nj][0] + s[nj][1];
            rs1 += s[nj][2] + s[nj][3];
        }
        rs0 += __shfl_xor_sync(0xffffffffu, rs0, 1);
        rs0 += __shfl_xor_sync(0xffffffffu, rs0, 2);
        rs1 += __shfl_xor_sync(0xffffffffu, rs1, 1);
        rs1 += __shfl_xor_sync(0xffffffffu, rs1, 2);
        l0 = l0 * al0 + rs0;  m0 = nm0;
        l1 = l1 * al1 + rs1;  m1 = nm1;

#pragma unroll
        for (int nj = 0; nj < 8; nj++) {
            o[nj][0] *= al0; o[nj][1] *= al0;
            o[nj][2] *= al1; o[nj][3] *= al1;
        }

        // ---- write P (tf32) to warp-private smem rows ----
#pragma unroll
        for (int nj = 0; nj < 8; nj++) {
            int col = nj * 8 + tg * 2;
            float2 p0 = make_float2(to_tf32(s[nj][0]), to_tf32(s[nj][1]));
            float2 p1 = make_float2(to_tf32(s[nj][2]), to_tf32(s[nj][3]));
            *(float2*)&Ps[(wrow + g    ) * FS + col] = p0;
            *(float2*)&Ps[(wrow + g + 8) * FS + col] = p1;
        }
        __syncwarp();

        // ---- O += P @ V (V loads conflict-free at stride VS=72) ----
#pragma unroll
        for (int ks = 0; ks < 8; ks++) {
            const int kk = ks * 8;
            uint32_t pa[4];
            ldm_x4(pa, sP + (uint32_t)((((wrow + arow) * FS) + kk + acol) * 4));
            uint32_t vb[8][2];
#pragma unroll
            for (int nj = 0; nj < 8; nj++) {
                int d = nj * 8 + g;
                vb[nj][0] = __float_as_uint(Vs[(kk + tg    ) * VS + d]);
                vb[nj][1] = __float_as_uint(Vs[(kk + tg + 4) * VS + d]);
            }
#pragma unroll
            for (int nj = 0; nj < 8; nj++)
                mma_tf32(o[nj], pa, vb[nj]);
        }

        cp_wait0();
        __syncthreads();
    }

    // ---- epilogue ----
    float inv0 = 1.0f / l0, inv1 = 1.0f / l1;
#pragma unroll
    for (int nj = 0; nj < 8; nj++) {
        int col = h * HD + nj * 8 + tg * 2;
        int rr = q0 + wrow + g;
        float2 v0 = make_float2(to_tf32(o[nj][0] * inv0), to_tf32(o[nj][1] * inv0));
        float2 v1 = make_float2(to_tf32(o[nj][2] * inv1), to_tf32(o[nj][3] * inv1));
        *(float2*)(outp + (size_t)(rr * B_DIM + b) * E_DIM + col)       = v0;
        *(float2*)(outp + (size_t)((rr + 8) * B_DIM + b) * E_DIM + col) = v1;
    }
#undef KV_STAGE
}

// ---------------------------------------------------------------------------
// Launch
// ---------------------------------------------------------------------------
extern "C" void kernel_launch(void* const* d_in, const int* in_sizes, int n_in,
                              void* d_out, int out_size)
{
    const float* x    = (const float*)d_in[0];
    const float* wqkv = (const float*)d_in[1];
    const float* bqkv = (const float*)d_in[2];
    const float* wout = (const float*)d_in[3];
    const float* bout = (const float*)d_in[4];
    float* out = (float*)d_out;

    float *qkv, *attn, *xr, *wqkvr, *woutr;
    cudaGetSymbolAddress((void**)&qkv,   g_qkv);
    cudaGetSymbolAddress((void**)&attn,  g_attn);
    cudaGetSymbolAddress((void**)&xr,    g_xr);
    cudaGetSymbolAddress((void**)&wqkvr, g_wqkvr);
    cudaGetSymbolAddress((void**)&woutr, g_woutr);

    const size_t GEMM_SMEM  = (size_t)3 * 2 * 128 * GS * sizeof(float);            // 110592
    const size_t FLASH_SMEM = (size_t)(2 * 64 * FS + 2 * 64 * VS + 128 * FS) * 4;  // 106496
    cudaFuncSetAttribute(gemm_tf32_kernel<1>,
                         cudaFuncAttributeMaxDynamicSharedMemorySize, (int)GEMM_SMEM);
    cudaFuncSetAttribute(gemm_tf32_kernel<0>,
                         cudaFuncAttributeMaxDynamicSharedMemorySize, (int)GEMM_SMEM);
    cudaFuncSetAttribute(flash_tf32_kernel,
                         cudaFuncAttributeMaxDynamicSharedMemorySize, (int)FLASH_SMEM);

    // 0) fused prepass: round inputs to tf32
    {
        int total = NX4 + NW14 + NW24;
        round_all_kernel<<<(total + 255) / 256, 256>>>(
            (const float4*)x, (float4*)xr,
            (const float4*)wqkv, (float4*)wqkvr,
            (const float4*)wout, (float4*)woutr);
    }

    // 1) QKV projection (rounded output, Q pre-scaled by 0.125*log2e)
    {
        dim3 grid(QKV_N / 128, M_ROWS / 128);
        gemm_tf32_kernel<1><<<grid, 256, GEMM_SMEM>>>(xr, wqkvr, bqkv, qkv,
                                                      M_ROWS, QKV_N, E_DIM);
    }
    // 2) Attention (exp2-domain softmax)
    {
        dim3 grid(L_DIM / 128, B_DIM * H_DIM);
        flash_tf32_kernel<<<grid, 256, FLASH_SMEM>>>(qkv, attn);
    }
    // 3) Output projection (full fp32 output)
    {
        dim3 grid(E_DIM / 128, M_ROWS / 128);
        gemm_tf32_kernel<0><<<grid, 256, GEMM_SMEM>>>(attn, woutr, bout, out,
                                                      M_ROWS, E_DIM, E_DIM);
    }
}

// round 10
// speedup vs baseline: 2.9767x; 1.8270x over previous
#include <cuda_runtime.h>
#include <cuda_fp16.h>
#include <math.h>
#include <stdint.h>

// Problem constants
#define L_DIM 1024
#define B_DIM 8
#define E_DIM 1024
#define H_DIM 16
#define HD    64
#define M_ROWS (L_DIM * B_DIM)      // 8192
#define QKV_N  (3 * E_DIM)          // 3072
#define ROW3E  (3 * E_DIM)

// Scratch (allocation-free rule: __device__ globals), all fp16 now
__device__ __half g_qkv[(size_t)M_ROWS * QKV_N];   // fp16, Q pre-scaled by 0.125*log2e
__device__ __half g_attn[(size_t)M_ROWS * E_DIM];  // fp16 attention output
__device__ __half g_xh[(size_t)M_ROWS * E_DIM];    // fp16 x
__device__ __half g_wqkvh[(size_t)QKV_N * E_DIM];  // fp16 Wqkv
__device__ __half g_wouth[(size_t)E_DIM * E_DIM];  // fp16 Wout

__device__ __forceinline__ void mma_f16(float* c, const uint32_t* a, const uint32_t* b) {
    asm volatile(
        "mma.sync.aligned.m16n8k16.row.col.f32.f16.f16.f32 "
        "{%0,%1,%2,%3}, {%4,%5,%6,%7}, {%8,%9}, {%0,%1,%2,%3};\n"
        : "+f"(c[0]), "+f"(c[1]), "+f"(c[2]), "+f"(c[3])
        : "r"(a[0]), "r"(a[1]), "r"(a[2]), "r"(a[3]),
          "r"(b[0]), "r"(b[1]));
}

__device__ __forceinline__ void cp16(uint32_t sdst, const void* gsrc) {
    asm volatile("cp.async.cg.shared.global [%0], [%1], 16;\n"
                 :: "r"(sdst), "l"(gsrc));
}
__device__ __forceinline__ void cp_commit() {
    asm volatile("cp.async.commit_group;\n" ::: "memory");
}
__device__ __forceinline__ void cp_wait0() {
    asm volatile("cp.async.wait_group 0;\n" ::: "memory");
}
__device__ __forceinline__ void cp_wait1() {
    asm volatile("cp.async.wait_group 1;\n" ::: "memory");
}

__device__ __forceinline__ void ldm_x4(uint32_t* r, uint32_t addr) {
    asm volatile("ldmatrix.sync.aligned.m8n8.x4.shared.b16 {%0,%1,%2,%3}, [%4];"
        : "=r"(r[0]), "=r"(r[1]), "=r"(r[2]), "=r"(r[3]) : "r"(addr));
}
__device__ __forceinline__ void ldm_x4t(uint32_t* r, uint32_t addr) {
    asm volatile("ldmatrix.sync.aligned.m8n8.x4.trans.shared.b16 {%0,%1,%2,%3}, [%4];"
        : "=r"(r[0]), "=r"(r[1]), "=r"(r[2]), "=r"(r[3]) : "r"(addr));
}

// ---------------------------------------------------------------------------
// Fused prepass: convert x, Wqkv, Wout to fp16 in one launch
// ---------------------------------------------------------------------------
#define NX4  (M_ROWS * E_DIM / 4)          // 2097152
#define NW14 (QKV_N * E_DIM / 4)           // 786432
#define NW24 (E_DIM * E_DIM / 4)           // 262144

__global__ void cvt_all_kernel(const float4* __restrict__ x,   __half2* __restrict__ xh,
                               const float4* __restrict__ wq,  __half2* __restrict__ wqh,
                               const float4* __restrict__ wo,  __half2* __restrict__ woh)
{
    int i = blockIdx.x * blockDim.x + threadIdx.x;
    const float4* src; __half2* dst; int j;
    if (i < NX4)                    { src = x;  dst = xh;  j = i; }
    else if (i < NX4 + NW14)        { src = wq; dst = wqh; j = i - NX4; }
    else if (i < NX4 + NW14 + NW24) { src = wo; dst = woh; j = i - NX4 - NW14; }
    else return;
    float4 v = src[j];
    dst[2 * j]     = __floats2half2_rn(v.x, v.y);
    dst[2 * j + 1] = __floats2half2_rn(v.z, v.w);
}

// ---------------------------------------------------------------------------
// FP16 GEMM: C[M,N] = A[M,K] @ W[N,K]^T + bias[N]  (fp32 accumulate)
// 256 threads = 8 warps (2x4 grid of 64x32 warp tiles), block tile 128x128,
// K-tile 64 halves, 3-stage cp.async pipeline, ldmatrix m16n8k16 fragments,
// smem row stride 72 halves (144 B) -> ldmatrix conflict-free. 2 CTAs/SM.
// MODE 0: fp32 out.  MODE 1: fp16 qkv out (Q cols scaled by 0.125*log2e).
// ---------------------------------------------------------------------------
#define GSH 72                       // smem row stride in halves
#define GROWB 144                    // row bytes
#define STAGE_BYTES (2 * 128 * GROWB)  // 36864
#define QSCALE (0.125f * 1.44269504088896340736f)

template<int MODE>
__global__ void __launch_bounds__(256, 2) gemm_f16_kernel(
    const __half* __restrict__ A, const __half* __restrict__ W,
    const float* __restrict__ bias, void* __restrict__ Cv,
    int M, int N, int K)
{
    extern __shared__ char smg[];
    const uint32_t sbase = (uint32_t)__cvta_generic_to_shared(smg);

    const int tid  = threadIdx.x;
    const int lane = tid & 31;
    const int wid  = tid >> 5;
    const int wm   = (wid >> 2) * 64;
    const int wn   = (wid & 3) * 32;
    const int rowBase = blockIdx.y * 128;
    const int colBase = blockIdx.x * 128;

    // cp.async loader: rows r0+32p, 16B chunk c8 (8 halves)
    const int r0 = tid >> 3;
    const int c8 = (tid & 7) * 8;
    const __half* Aptr = A + (size_t)(rowBase + r0) * K + c8;
    const __half* Wptr = W + (size_t)(colBase + r0) * K + c8;

    // ldmatrix lane address components (halves)
    const int arow = (lane & 15);
    const int acol = (lane >> 4) * 8;            // 0 or 8 halves (k half-step)
    const int brow = ((lane >> 4) << 3) + (lane & 7);
    const int bcol = ((lane >> 3) & 1) * 8;

    float c[4][4][4];
#pragma unroll
    for (int mi = 0; mi < 4; mi++)
#pragma unroll
        for (int nj = 0; nj < 4; nj++)
#pragma unroll
            for (int r = 0; r < 4; r++) c[mi][nj][r] = 0.f;

#define GEMM_STAGE(buf, k0)                                                    \
    {                                                                          \
        uint32_t sb_ = sbase + (uint32_t)((buf) * STAGE_BYTES);                \
        _Pragma("unroll")                                                      \
        for (int p = 0; p < 4; p++) {                                          \
            uint32_t so_ = (uint32_t)((r0 + p * 32) * GROWB + (tid & 7) * 16); \
            cp16(sb_ + so_,                       Aptr + (size_t)(p * 32) * K + (k0)); \
            cp16(sb_ + (uint32_t)(128 * GROWB) + so_, Wptr + (size_t)(p * 32) * K + (k0)); \
        }                                                                      \
        cp_commit();                                                           \
    }

    const int T = K >> 6;   // 16 for K=1024
    GEMM_STAGE(0, 0);
    GEMM_STAGE(1, 64);

    int cbuf = 0;
    for (int t = 0; t < T; t++) {
        if (t == T - 1) cp_wait0(); else cp_wait1();
        __syncthreads();

        if (t + 2 < T) {
            int nb = cbuf + 2; if (nb >= 3) nb -= 3;
            GEMM_STAGE(nb, (t + 2) << 6);
        }

        const uint32_t Ab = sbase + (uint32_t)(cbuf * STAGE_BYTES);
        const uint32_t Wb = Ab + (uint32_t)(128 * GROWB);
#pragma unroll
        for (int ks = 0; ks < 4; ks++) {
            const int kk = ks * 16;
            uint32_t a[4][4], b[4][2];
#pragma unroll
            for (int mi = 0; mi < 4; mi++)
                ldm_x4(a[mi], Ab + (uint32_t)((wm + mi * 16 + arow) * GROWB + (kk + acol) * 2));
#pragma unroll
            for (int njp = 0; njp < 2; njp++)
                ldm_x4(&b[njp * 2][0],
                       Wb + (uint32_t)((wn + njp * 16 + brow) * GROWB + (kk + bcol) * 2));
#pragma unroll
            for (int mi = 0; mi < 4; mi++)
#pragma unroll
                for (int nj = 0; nj < 4; nj++)
                    mma_f16(c[mi][nj], a[mi], b[nj]);
        }
        cbuf++; if (cbuf == 3) cbuf = 0;
    }

    // epilogue
    const int g  = lane >> 2;
    const int tg = lane & 3;
    float scale = 1.f;
    if (MODE == 1) scale = (colBase < E_DIM) ? QSCALE : 1.f;
#pragma unroll
    for (int mi = 0; mi < 4; mi++) {
#pragma unroll
        for (int nj = 0; nj < 4; nj++) {
            int row0 = rowBase + wm + mi * 16 + g;
            int col  = colBase + wn + nj * 8 + tg * 2;
            float b0 = bias[col], b1 = bias[col + 1];
            if (MODE == 1) {
                __half* Ch = (__half*)Cv;
                __half2 v0 = __floats2half2_rn((c[mi][nj][0] + b0) * scale,
                                               (c[mi][nj][1] + b1) * scale);
                __half2 v1 = __floats2half2_rn((c[mi][nj][2] + b0) * scale,
                                               (c[mi][nj][3] + b1) * scale);
                *(__half2*)(Ch + (size_t)row0 * N + col)       = v0;
                *(__half2*)(Ch + (size_t)(row0 + 8) * N + col) = v1;
            } else {
                float* Cf = (float*)Cv;
                float2 v0 = make_float2(c[mi][nj][0] + b0, c[mi][nj][1] + b1);
                float2 v1 = make_float2(c[mi][nj][2] + b0, c[mi][nj][3] + b1);
                *(float2*)(Cf + (size_t)row0 * N + col)       = v0;
                *(float2*)(Cf + (size_t)(row0 + 8) * N + col) = v1;
            }
        }
    }
#undef GEMM_STAGE
}

// ---------------------------------------------------------------------------
// FP16 flash attention (fp32 softmax/accumulators), double-buffered K/V.
// One block = (b,h) x 128 q-rows, 256 thr (8 warps), warp owns 16 S rows.
// All smem tiles at row stride 72 halves (144 B): ldmatrix conflict-free,
// V read via ldmatrix.x4.trans (no scalar LDS). Softmax in exp2 domain.
// smem: K 2x64x72 + V 2x64x72 + Ps 128x72 halves = 55296 B -> 2 CTAs/SM.
// ---------------------------------------------------------------------------
__global__ void __launch_bounds__(256, 2) flash_f16_kernel(
    const __half* __restrict__ qkv, __half* __restrict__ outp)
{
    extern __shared__ __half smh[];
    __half* Kb0 = smh;                      // 64*GSH
    __half* Kb1 = Kb0 + 64 * GSH;
    __half* Vb0 = Kb1 + 64 * GSH;
    __half* Vb1 = Vb0 + 64 * GSH;
    __half* Ps  = Vb1 + 64 * GSH;           // 128*GSH (Q staging, then P)
    const uint32_t sK0 = (uint32_t)__cvta_generic_to_shared(Kb0);
    const uint32_t sV0 = (uint32_t)__cvta_generic_to_shared(Vb0);
    const uint32_t sP  = (uint32_t)__cvta_generic_to_shared(Ps);
    const uint32_t BUF = (uint32_t)(64 * GROWB);   // 9216 B per K or V buffer

    const int tid  = threadIdx.x;
    const int wid  = tid >> 5;
    const int lane = tid & 31;
    const int g    = lane >> 2;
    const int tg   = lane & 3;
    const int wrow = wid * 16;

    const int bh = blockIdx.y;
    const int b  = bh >> 4;
    const int h  = bh & 15;
    const int q0 = blockIdx.x * 128;

    const size_t rstride = (size_t)B_DIM * ROW3E;   // 24576 halves

    // ldmatrix lane address components
    const int arow = (lane & 15);
    const int acol = (lane >> 4) * 8;
    const int brow = ((lane >> 4) << 3) + (lane & 7);
    const int bcol = ((lane >> 3) & 1) * 8;
    // V trans components: token row = lane&15, d half-group = (lane>>4)*8
    const int vrow = (lane & 15);
    const int vcol = (lane >> 4) * 8;

    // K/V loader: 64 rows x 8 chunks = 512 chunks, 2 per thread
    const int r0 = tid >> 3;               // 0..31, +p*32
    const int c8 = (tid & 7) * 8;          // halves
    const __half* kbase0 = qkv + (size_t)b * ROW3E + E_DIM + h * HD;

#define KV_STAGE(kt, buf)                                                      \
    {                                                                          \
        uint32_t sKb_ = sK0 + (buf) * BUF;                                     \
        uint32_t sVb_ = sV0 + (buf) * BUF;                                     \
        _Pragma("unroll")                                                      \
        for (int p = 0; p < 2; p++) {                                          \
            int rr_ = r0 + p * 32;                                             \
            uint32_t so_ = (uint32_t)(rr_ * GROWB + (tid & 7) * 16);           \
            const __half* kb_ = kbase0 + (size_t)((kt) * 64 + rr_) * rstride + c8; \
            cp16(sKb_ + so_, kb_);                                             \
            cp16(sVb_ + so_, kb_ + E_DIM);                                     \
        }                                                                      \
        cp_commit();                                                           \
    }

    // ---- stage Q (pre-scaled fp16) into Ps, and KV tile 0 ----
    {
        const __half* qbase = qkv + (size_t)(q0 * B_DIM + b) * ROW3E + h * HD;
#pragma unroll
        for (int p = 0; p < 4; p++) {
            int f4 = tid + p * 256;
            int r  = f4 >> 3;              // 0..127
            int cc = (f4 & 7) * 8;
            cp16(sP + (uint32_t)(r * GROWB + (f4 & 7) * 16),
                 qbase + (size_t)r * rstride + cc);
        }
    }
    KV_STAGE(0, 0);
    cp_wait0();
    __syncthreads();

    // ---- Q fragments into registers (warp-private rows) ----
    uint32_t qa[4][4];
#pragma unroll
    for (int ks = 0; ks < 4; ks++)
        ldm_x4(qa[ks], sP + (uint32_t)((wrow + arow) * GROWB + (ks * 16 + acol) * 2));
    __syncwarp();

    float o[8][4];
#pragma unroll
    for (int nj = 0; nj < 8; nj++)
#pragma unroll
        for (int r = 0; r < 4; r++) o[nj][r] = 0.f;
    float m0 = -1e30f, m1 = -1e30f, l0 = 0.f, l1 = 0.f;

    for (int kt = 0; kt < 16; kt++) {
        const int cur = kt & 1;
        if (kt + 1 < 16) KV_STAGE(kt + 1, 1 - cur);

        const uint32_t sKc = sK0 + cur * BUF;
        const uint32_t sVc = sV0 + cur * BUF;

        // ---- S = Q K^T (log2-units) ----
        float s[8][4];
#pragma unroll
        for (int nj = 0; nj < 8; nj++)
#pragma unroll
            for (int r = 0; r < 4; r++) s[nj][r] = 0.f;

#pragma unroll
        for (int ks = 0; ks < 4; ks++) {
            const int kk = ks * 16;
            uint32_t kb[8][2];
#pragma unroll
            for (int njp = 0; njp < 4; njp++)
                ldm_x4(&kb[njp * 2][0],
                       sKc + (uint32_t)((njp * 16 + brow) * GROWB + (kk + bcol) * 2));
#pragma unroll
            for (int nj = 0; nj < 8; nj++)
                mma_f16(s[nj], qa[ks], kb[nj]);
        }

        // ---- online softmax, exp2 domain ----
        float rmax0 = -1e30f, rmax1 = -1e30f;
#pragma unroll
        for (int nj = 0; nj < 8; nj++) {
            rmax0 = fmaxf(rmax0, fmaxf(s[nj][0], s[nj][1]));
            rmax1 = fmaxf(rmax1, fmaxf(s[nj][2], s[nj][3]));
        }
        rmax0 = fmaxf(rmax0, __shfl_xor_sync(0xffffffffu, rmax0, 1));
        rmax0 = fmaxf(rmax0, __shfl_xor_sync(0xffffffffu, rmax0, 2));
        rmax1 = fmaxf(rmax1, __shfl_xor_sync(0xffffffffu, rmax1, 1));
        rmax1 = fmaxf(rmax1, __shfl_xor_sync(0xffffffffu, rmax1, 2));

        float nm0 = fmaxf(m0, rmax0), nm1 = fmaxf(m1, rmax1);
        float al0 = exp2f(m0 - nm0), al1 = exp2f(m1 - nm1);
        float rs0 = 0.f, rs1 = 0.f;
#pragma unroll
        for (int nj = 0; nj < 8; nj++) {
            s[nj][0] = exp2f(s[nj][0] - nm0);
            s[nj][1] = exp2f(s[nj][1] - nm0);
            s[nj][2] = exp2f(s[nj][2] - nm1);
            s[nj][3] = exp2f(s[nj][3] - nm1);
            rs0 += s[nj][0] + s[nj][1];
            rs1 += s[nj][2] + s[nj][3];
        }
        rs0 += __shfl_xor_sync(0xffffffffu, rs0, 1);
        rs0 += __shfl_xor_sync(0xffffffffu, rs0, 2);
        rs1 += __shfl_xor_sync(0xffffffffu, rs1, 1);
        rs1 += __shfl_xor_sync(0xffffffffu, rs1, 2);
        l0 = l0 * al0 + rs0;  m0 = nm0;
        l1 = l1 * al1 + rs1;  m1 = nm1;

#pragma unroll
        for (int nj = 0; nj < 8; nj++) {
            o[nj][0] *= al0; o[nj][1] *= al0;
            o[nj][2] *= al1; o[nj][3] *= al1;
        }

        // ---- write P (fp16) to warp-private smem rows (conflict-free) ----
#pragma unroll
        for (int nj = 0; nj < 8; nj++) {
            int col = nj * 8 + tg * 2;
            *(__half2*)&Ps[(wrow + g    ) * GSH + col] = __floats2half2_rn(s[nj][0], s[nj][1]);
            *(__half2*)&Ps[(wrow + g + 8) * GSH + col] = __floats2half2_rn(s[nj][2], s[nj][3]);
        }
        __syncwarp();

        // ---- O += P @ V (V via ldmatrix.trans) ----
#pragma unroll
        for (int ks = 0; ks < 4; ks++) {
            const int kk = ks * 16;
            uint32_t pa[4];
            ldm_x4(pa, sP + (uint32_t)((wrow + arow) * GROWB + (kk + acol) * 2));
            uint32_t vb[8][2];
#pragma unroll
            for (int njp = 0; njp < 4; njp++)
                ldm_x4t(&vb[njp * 2][0],
                        sVc + (uint32_t)((kk + vrow) * GROWB + (njp * 16 + vcol) * 2));
#pragma unroll
            for (int nj = 0; nj < 8; nj++)
                mma_f16(o[nj], pa, vb[nj]);
        }

        cp_wait0();
        __syncthreads();
    }

    // ---- epilogue: normalize, fp16 out to [L,B,E] ----
    float inv0 = 1.0f / l0, inv1 = 1.0f / l1;
#pragma unroll
    for (int nj = 0; nj < 8; nj++) {
        int col = h * HD + nj * 8 + tg * 2;
        int rr = q0 + wrow + g;
        __half2 v0 = __floats2half2_rn(o[nj][0] * inv0, o[nj][1] * inv0);
        __half2 v1 = __floats2half2_rn(o[nj][2] * inv1, o[nj][3] * inv1);
        *(__half2*)(outp + (size_t)(rr * B_DIM + b) * E_DIM + col)       = v0;
        *(__half2*)(outp + (size_t)((rr + 8) * B_DIM + b) * E_DIM + col) = v1;
    }
#undef KV_STAGE
}

// ---------------------------------------------------------------------------
// Launch
// ---------------------------------------------------------------------------
extern "C" void kernel_launch(void* const* d_in, const int* in_sizes, int n_in,
                              void* d_out, int out_size)
{
    const float* x    = (const float*)d_in[0];
    const float* wqkv = (const float*)d_in[1];
    const float* bqkv = (const float*)d_in[2];
    const float* wout = (const float*)d_in[3];
    const float* bout = (const float*)d_in[4];
    float* out = (float*)d_out;

    __half *qkv, *attn, *xh, *wqkvh, *wouth;
    cudaGetSymbolAddress((void**)&qkv,   g_qkv);
    cudaGetSymbolAddress((void**)&attn,  g_attn);
    cudaGetSymbolAddress((void**)&xh,    g_xh);
    cudaGetSymbolAddress((void**)&wqkvh, g_wqkvh);
    cudaGetSymbolAddress((void**)&wouth, g_wouth);

    const size_t GEMM_SMEM  = (size_t)3 * STAGE_BYTES;                 // 110592
    const size_t FLASH_SMEM = (size_t)(4 * 64 + 128) * GROWB;          // 55296
    cudaFuncSetAttribute(gemm_f16_kernel<1>,
                         cudaFuncAttributeMaxDynamicSharedMemorySize, (int)GEMM_SMEM);
    cudaFuncSetAttribute(gemm_f16_kernel<0>,
                         cudaFuncAttributeMaxDynamicSharedMemorySize, (int)GEMM_SMEM);
    cudaFuncSetAttribute(flash_f16_kernel,
                         cudaFuncAttributeMaxDynamicSharedMemorySize, (int)FLASH_SMEM);

    // 0) fused prepass: convert inputs to fp16
    {
        int total = NX4 + NW14 + NW24;
        cvt_all_kernel<<<(total + 255) / 256, 256>>>(
            (const float4*)x, (__half2*)xh,
            (const float4*)wqkv, (__half2*)wqkvh,
            (const float4*)wout, (__half2*)wouth);
    }

    // 1) QKV projection (fp16 out, Q pre-scaled by 0.125*log2e)
    {
        dim3 grid(QKV_N / 128, M_ROWS / 128);
        gemm_f16_kernel<1><<<grid, 256, GEMM_SMEM>>>(xh, wqkvh, bqkv, qkv,
                                                     M_ROWS, QKV_N, E_DIM);
    }
    // 2) Attention (exp2-domain softmax, fp16 operands)
    {
        dim3 grid(L_DIM / 128, B_DIM * H_DIM);
        flash_f16_kernel<<<grid, 256, FLASH_SMEM>>>(qkv, attn);
    }
    // 3) Output projection (fp32 out)
    {
        dim3 grid(E_DIM / 128, M_ROWS / 128);
        gemm_f16_kernel<0><<<grid, 256, GEMM_SMEM>>>(attn, wouth, bout, out,
                                                     M_ROWS, E_DIM, E_DIM);
    }
}